// round 1
// baseline (speedup 1.0000x reference)
#include <cuda_runtime.h>
#include <math.h>

#define B_ 2
#define S_ 2048
#define H_ 1024
#define NH_ 16
#define HD_ 64
#define H3_ 3072
#define R_ 4096   // B*S

// ---- scratch (static device globals; no runtime allocation) ----
__device__ float g_mod[B_ * H3_];                 // [B, 3H]  (scale | shift | gate)
__device__ float g_h[(size_t)R_ * H_];            // modulated LN output
__device__ float g_qkv[(size_t)R_ * H3_];         // qkv projections (q,k normalized+rope in-place)
__device__ float g_o[(size_t)R_ * H_];            // attention output, [B,S,H] layout

__device__ __forceinline__ float warp_sum(float v) {
#pragma unroll
    for (int o = 16; o; o >>= 1) v += __shfl_xor_sync(0xffffffffu, v, o);
    return v;
}

// ============================================================
// 1) mod = silu(ada) @ mod_w^T + mod_b       (one warp per output)
// ============================================================
__global__ void __launch_bounds__(256) mod_kernel(const float* __restrict__ ada,
                                                  const float* __restrict__ mw,
                                                  const float* __restrict__ mb) {
    int gw = (blockIdx.x * 256 + threadIdx.x) >> 5;    // 0..6143
    int lane = threadIdx.x & 31;
    int b = gw / H3_, j = gw % H3_;
    const float* ar = ada + b * 1024;
    const float* wr = mw + (size_t)j * 1024;
    float acc = 0.f;
#pragma unroll 4
    for (int a = lane; a < 1024; a += 32) {
        float v = ar[a];
        float s = v / (1.f + __expf(-v));              // silu
        acc = fmaf(s, wr[a], acc);
    }
    acc = warp_sum(acc);
    if (lane == 0) g_mod[gw] = acc + mb[j];
}

// ============================================================
// 2) h = LN(x)*ln_w*(scale+1) + shift        (one block per row)
// ============================================================
__global__ void __launch_bounds__(256) ln_mod_kernel(const float* __restrict__ x,
                                                     const float* __restrict__ ln_w) {
    int row = blockIdx.x;
    int tid = threadIdx.x;
    int b = row >> 11;   // S=2048

    float4 xv = ((const float4*)x)[(size_t)row * 256 + tid];
    float sum = xv.x + xv.y + xv.z + xv.w;
    float sq  = xv.x * xv.x + xv.y * xv.y + xv.z * xv.z + xv.w * xv.w;
    sum = warp_sum(sum);
    sq  = warp_sum(sq);

    __shared__ float rs[8], rq[8], mv[2];
    int warp = tid >> 5, lane = tid & 31;
    if (lane == 0) { rs[warp] = sum; rq[warp] = sq; }
    __syncthreads();
    if (tid == 0) {
        float s = 0.f, q = 0.f;
#pragma unroll
        for (int w = 0; w < 8; ++w) { s += rs[w]; q += rq[w]; }
        float mean = s * (1.f / 1024.f);
        float var  = q * (1.f / 1024.f) - mean * mean;
        mv[0] = mean;
        mv[1] = rsqrtf(var + 1e-5f);
    }
    __syncthreads();
    float mean = mv[0], rstd = mv[1];

    float4 lw = ((const float4*)ln_w)[tid];
    const float* mp = g_mod + b * H3_;
    float4 sc = ((const float4*)mp)[tid];
    float4 sh = ((const float4*)(mp + H_))[tid];

    float4 h;
    h.x = (xv.x - mean) * rstd * lw.x * (sc.x + 1.f) + sh.x;
    h.y = (xv.y - mean) * rstd * lw.y * (sc.y + 1.f) + sh.y;
    h.z = (xv.z - mean) * rstd * lw.z * (sc.z + 1.f) + sh.z;
    h.w = (xv.w - mean) * rstd * lw.w * (sc.w + 1.f) + sh.w;
    ((float4*)g_h)[(size_t)row * 256 + tid] = h;
}

// ============================================================
// 3/6) SGEMM NT: C[M,N] = A[M,1024] * B[N,1024]^T  (+optional gate epilogue)
//      BM=BN=64, BK=16, 256 threads, 4x4 micro-tile.
//      mode 0: A=g_h,  C=g_qkv           (qkv projection)
//      mode 1: A=g_o,  C=Cext, *gate     (output projection)
// ============================================================
__global__ void __launch_bounds__(256) sgemm_kernel(const float* __restrict__ Bm,
                                                    float* __restrict__ Cext,
                                                    int N, int mode) {
    const int K = 1024;
    const float* A = mode ? g_o : g_h;
    float* C = mode ? Cext : g_qkv;

    __shared__ float As[16][64];
    __shared__ float Bs[16][64];

    int tid = threadIdx.x;
    int tx = tid & 15, ty = tid >> 4;
    int row0 = blockIdx.y * 64, col0 = blockIdx.x * 64;
    int lr = tid >> 2;            // 0..63
    int lk = (tid & 3) * 4;       // 0,4,8,12

    const float* Ap = A + (size_t)(row0 + lr) * K + lk;
    const float* Bp = Bm + (size_t)(col0 + lr) * K + lk;

    float acc[4][4] = {};

    for (int k0 = 0; k0 < K; k0 += 16) {
        float4 av = *(const float4*)(Ap + k0);
        float4 bv = *(const float4*)(Bp + k0);
        As[lk + 0][lr] = av.x; As[lk + 1][lr] = av.y;
        As[lk + 2][lr] = av.z; As[lk + 3][lr] = av.w;
        Bs[lk + 0][lr] = bv.x; Bs[lk + 1][lr] = bv.y;
        Bs[lk + 2][lr] = bv.z; Bs[lk + 3][lr] = bv.w;
        __syncthreads();
#pragma unroll
        for (int kk = 0; kk < 16; ++kk) {
            float4 a = ((const float4*)As[kk])[ty];
            float4 b4 = ((const float4*)Bs[kk])[tx];
            float av4[4] = {a.x, a.y, a.z, a.w};
            float bv4[4] = {b4.x, b4.y, b4.z, b4.w};
#pragma unroll
            for (int i = 0; i < 4; ++i)
#pragma unroll
                for (int j = 0; j < 4; ++j)
                    acc[i][j] = fmaf(av4[i], bv4[j], acc[i][j]);
        }
        __syncthreads();
    }

#pragma unroll
    for (int i = 0; i < 4; ++i) {
        int r = row0 + ty * 4 + i;
        int c = col0 + tx * 4;
        float4 v = make_float4(acc[i][0], acc[i][1], acc[i][2], acc[i][3]);
        if (mode) {
            const float* gp = g_mod + (r >> 11) * H3_ + 2 * H_ + c;
            v.x *= gp[0]; v.y *= gp[1]; v.z *= gp[2]; v.w *= gp[3];
        }
        *(float4*)(C + (size_t)r * N + c) = v;
    }
}

// ============================================================
// 4) per-head QK layernorm + RoPE, in place on g_qkv
//    one block per (b,s) row; warp-per-(head,q/k) tasks
// ============================================================
__global__ void __launch_bounds__(256) qknorm_rope_kernel(const float* __restrict__ freqs,
                                                          const float* __restrict__ qn_w,
                                                          const float* __restrict__ kn_w) {
    int row = blockIdx.x;            // 0..4095
    int s = row & (S_ - 1);
    int warp = threadIdx.x >> 5;
    int lane = threadIdx.x & 31;

    float f0 = freqs[(s * 32 + lane) * 2 + 0];
    float f1 = freqs[(s * 32 + lane) * 2 + 1];

    for (int task = warp; task < 32; task += 8) {
        int type = task >> 4;        // 0=q, 1=k
        int head = task & 15;
        size_t base = (size_t)row * H3_ + type * H_ + head * HD_;
        float v0 = g_qkv[base + lane * 2];
        float v1 = g_qkv[base + lane * 2 + 1];
        float sum = warp_sum(v0 + v1);
        float sq  = warp_sum(v0 * v0 + v1 * v1);
        float mean = sum * (1.f / 64.f);
        float var  = sq * (1.f / 64.f) - mean * mean;
        float rstd = rsqrtf(var + 1e-5f);
        const float* w = type ? kn_w : qn_w;
        float n0 = (v0 - mean) * rstd * w[lane * 2];
        float n1 = (v1 - mean) * rstd * w[lane * 2 + 1];
        g_qkv[base + lane * 2]     = n0 * f0 - n1 * f1;
        g_qkv[base + lane * 2 + 1] = n1 * f0 + n0 * f1;
    }
}

// ============================================================
// 5) flash attention (non-causal), fp32
//    grid = (S/64 qtiles, B*NH heads), 256 threads
//    BQ=64, BK=32; thread grid 16(ty q) x 16(tx), 4q x 2k scores, 4q x 4d output
// ============================================================
__global__ void __launch_bounds__(256) attn_kernel() {
    __shared__ float Qs[64 * 64];   // [d][q], pre-scaled by 1/8
    __shared__ float Ks[64 * 32];   // [d][k]
    __shared__ float Vs[32 * 64];   // [k][d]
    __shared__ float Ps[64 * 33];   // [q][k], padded

    int tid = threadIdx.x;
    int tx = tid & 15, ty = tid >> 4;
    int q0 = blockIdx.x * 64;
    int bh = blockIdx.y;
    int b = bh >> 4, head = bh & 15;

    const float* baseQ = g_qkv + (size_t)(b * S_ + q0) * H3_ + head * HD_;
    {
        int lr = tid >> 2;          // q row 0..63
        int lc = (tid & 3) * 4;
#pragma unroll
        for (int c = 0; c < 4; ++c) {
            int d = c * 16 + lc;
            float4 v = *(const float4*)(baseQ + (size_t)lr * H3_ + d);
            Qs[(d + 0) * 64 + lr] = v.x * 0.125f;
            Qs[(d + 1) * 64 + lr] = v.y * 0.125f;
            Qs[(d + 2) * 64 + lr] = v.z * 0.125f;
            Qs[(d + 3) * 64 + lr] = v.w * 0.125f;
        }
    }

    float m[4], l[4], o[4][4];
#pragma unroll
    for (int i = 0; i < 4; ++i) {
        m[i] = -1e30f; l[i] = 0.f;
#pragma unroll
        for (int j = 0; j < 4; ++j) o[i][j] = 0.f;
    }

    int lr2 = tid >> 3;             // key row 0..31
    int lc2 = (tid & 7) * 8;        // d chunk

    for (int s0 = 0; s0 < S_; s0 += 32) {
        __syncthreads();            // prior PV reads of Ks/Vs/Ps done
        const float* baseK = g_qkv + (size_t)(b * S_ + s0) * H3_ + H_ + head * HD_;
        const float* baseV = baseK + H_;
        {
            float4 k0 = *(const float4*)(baseK + (size_t)lr2 * H3_ + lc2);
            float4 k1 = *(const float4*)(baseK + (size_t)lr2 * H3_ + lc2 + 4);
            Ks[(lc2 + 0) * 32 + lr2] = k0.x;
            Ks[(lc2 + 1) * 32 + lr2] = k0.y;
            Ks[(lc2 + 2) * 32 + lr2] = k0.z;
            Ks[(lc2 + 3) * 32 + lr2] = k0.w;
            Ks[(lc2 + 4) * 32 + lr2] = k1.x;
            Ks[(lc2 + 5) * 32 + lr2] = k1.y;
            Ks[(lc2 + 6) * 32 + lr2] = k1.z;
            Ks[(lc2 + 7) * 32 + lr2] = k1.w;
            float4 v0 = *(const float4*)(baseV + (size_t)lr2 * H3_ + lc2);
            float4 v1 = *(const float4*)(baseV + (size_t)lr2 * H3_ + lc2 + 4);
            *(float4*)(Vs + lr2 * 64 + lc2)     = v0;
            *(float4*)(Vs + lr2 * 64 + lc2 + 4) = v1;
        }
        __syncthreads();

        // scores: 4q x 2k per thread over 64 dims
        float sc[4][2] = {};
#pragma unroll
        for (int d = 0; d < 64; ++d) {
            float4 a = *(const float4*)(Qs + d * 64 + ty * 4);
            float2 kb = *(const float2*)(Ks + d * 32 + tx * 2);
            float av4[4] = {a.x, a.y, a.z, a.w};
#pragma unroll
            for (int i = 0; i < 4; ++i) {
                sc[i][0] = fmaf(av4[i], kb.x, sc[i][0]);
                sc[i][1] = fmaf(av4[i], kb.y, sc[i][1]);
            }
        }

        // online softmax update (row reductions over tx lanes: bits 0..3)
#pragma unroll
        for (int i = 0; i < 4; ++i) {
            float tmax = fmaxf(sc[i][0], sc[i][1]);
#pragma unroll
            for (int off = 8; off; off >>= 1)
                tmax = fmaxf(tmax, __shfl_xor_sync(0xffffffffu, tmax, off));
            float nm = fmaxf(m[i], tmax);
            float alpha = __expf(m[i] - nm);
            m[i] = nm;
            float p0 = __expf(sc[i][0] - nm);
            float p1 = __expf(sc[i][1] - nm);
            Ps[(ty * 4 + i) * 33 + tx * 2 + 0] = p0;
            Ps[(ty * 4 + i) * 33 + tx * 2 + 1] = p1;
            float ps = p0 + p1;
#pragma unroll
            for (int off = 8; off; off >>= 1)
                ps += __shfl_xor_sync(0xffffffffu, ps, off);
            l[i] = l[i] * alpha + ps;
#pragma unroll
            for (int j = 0; j < 4; ++j) o[i][j] *= alpha;
        }
        __syncthreads();

        // O += P @ V
#pragma unroll 8
        for (int k = 0; k < 32; ++k) {
            float4 v = *(const float4*)(Vs + k * 64 + tx * 4);
#pragma unroll
            for (int i = 0; i < 4; ++i) {
                float p = Ps[(ty * 4 + i) * 33 + k];
                o[i][0] = fmaf(p, v.x, o[i][0]);
                o[i][1] = fmaf(p, v.y, o[i][1]);
                o[i][2] = fmaf(p, v.z, o[i][2]);
                o[i][3] = fmaf(p, v.w, o[i][3]);
            }
        }
    }

#pragma unroll
    for (int i = 0; i < 4; ++i) {
        float inv = 1.f / l[i];
        int row = b * S_ + q0 + ty * 4 + i;
        float4 out4 = make_float4(o[i][0] * inv, o[i][1] * inv,
                                  o[i][2] * inv, o[i][3] * inv);
        *(float4*)(g_o + (size_t)row * H_ + head * HD_ + tx * 4) = out4;
    }
}

// ============================================================
extern "C" void kernel_launch(void* const* d_in, const int* in_sizes, int n_in,
                              void* d_out, int out_size) {
    (void)in_sizes; (void)n_in; (void)out_size;
    const float* x     = (const float*)d_in[0];
    const float* ada   = (const float*)d_in[1];
    const float* freqs = (const float*)d_in[2];
    const float* w_qkv = (const float*)d_in[3];
    const float* w_o   = (const float*)d_in[4];
    const float* ln_w  = (const float*)d_in[5];
    const float* mod_w = (const float*)d_in[6];
    const float* mod_b = (const float*)d_in[7];
    const float* qn_w  = (const float*)d_in[8];
    const float* kn_w  = (const float*)d_in[9];
    float* out = (float*)d_out;

    mod_kernel<<<768, 256>>>(ada, mod_w, mod_b);                       // 6144 warps
    ln_mod_kernel<<<R_, 256>>>(x, ln_w);
    sgemm_kernel<<<dim3(H3_ / 64, R_ / 64), 256>>>(w_qkv, nullptr, H3_, 0);
    qknorm_rope_kernel<<<R_, 256>>>(freqs, qn_w, kn_w);
    attn_kernel<<<dim3(S_ / 64, B_ * NH_), 256>>>();
    sgemm_kernel<<<dim3(H_ / 64, R_ / 64), 256>>>(w_o, out, H_, 1);
}

// round 2
// speedup vs baseline: 1.0001x; 1.0001x over previous
#include <cuda_runtime.h>
#include <math.h>

#define B_ 2
#define S_ 2048
#define H_ 1024
#define NH_ 16
#define HD_ 64
#define H3_ 3072
#define R_ 4096   // B*S

// ---- scratch (static device globals; no runtime allocation) ----
__device__ float g_mod[B_ * H3_];                 // [B, 3H]  (scale | shift | gate)
__device__ float g_h[(size_t)R_ * H_];            // modulated LN output
__device__ float g_qkv[(size_t)R_ * H3_];         // qkv projections (q,k normalized+rope in-place)
__device__ float g_o[(size_t)R_ * H_];            // attention output, [B,S,H] layout

__device__ __forceinline__ float warp_sum(float v) {
#pragma unroll
    for (int o = 16; o; o >>= 1) v += __shfl_xor_sync(0xffffffffu, v, o);
    return v;
}

// ============================================================
// 1) mod = silu(ada) @ mod_w^T + mod_b       (one warp per output)
// ============================================================
__global__ void __launch_bounds__(256) mod_kernel(const float* __restrict__ ada,
                                                  const float* __restrict__ mw,
                                                  const float* __restrict__ mb) {
    int gw = (blockIdx.x * 256 + threadIdx.x) >> 5;    // 0..6143
    int lane = threadIdx.x & 31;
    int b = gw / H3_, j = gw % H3_;
    const float* ar = ada + b * 1024;
    const float* wr = mw + (size_t)j * 1024;
    float acc = 0.f;
#pragma unroll 4
    for (int a = lane; a < 1024; a += 32) {
        float v = ar[a];
        float s = v / (1.f + __expf(-v));              // silu
        acc = fmaf(s, wr[a], acc);
    }
    acc = warp_sum(acc);
    if (lane == 0) g_mod[gw] = acc + mb[j];
}

// ============================================================
// 2) h = LN(x)*ln_w*(scale+1) + shift        (one block per row)
// ============================================================
__global__ void __launch_bounds__(256) ln_mod_kernel(const float* __restrict__ x,
                                                     const float* __restrict__ ln_w) {
    int row = blockIdx.x;
    int tid = threadIdx.x;
    int b = row >> 11;   // S=2048

    float4 xv = ((const float4*)x)[(size_t)row * 256 + tid];
    float sum = xv.x + xv.y + xv.z + xv.w;
    float sq  = xv.x * xv.x + xv.y * xv.y + xv.z * xv.z + xv.w * xv.w;
    sum = warp_sum(sum);
    sq  = warp_sum(sq);

    __shared__ float rs[8], rq[8], mv[2];
    int warp = tid >> 5, lane = tid & 31;
    if (lane == 0) { rs[warp] = sum; rq[warp] = sq; }
    __syncthreads();
    if (tid == 0) {
        float s = 0.f, q = 0.f;
#pragma unroll
        for (int w = 0; w < 8; ++w) { s += rs[w]; q += rq[w]; }
        float mean = s * (1.f / 1024.f);
        float var  = q * (1.f / 1024.f) - mean * mean;
        mv[0] = mean;
        mv[1] = rsqrtf(var + 1e-5f);
    }
    __syncthreads();
    float mean = mv[0], rstd = mv[1];

    float4 lw = ((const float4*)ln_w)[tid];
    const float* mp = g_mod + b * H3_;
    float4 sc = ((const float4*)mp)[tid];
    float4 sh = ((const float4*)(mp + H_))[tid];

    float4 h;
    h.x = (xv.x - mean) * rstd * lw.x * (sc.x + 1.f) + sh.x;
    h.y = (xv.y - mean) * rstd * lw.y * (sc.y + 1.f) + sh.y;
    h.z = (xv.z - mean) * rstd * lw.z * (sc.z + 1.f) + sh.z;
    h.w = (xv.w - mean) * rstd * lw.w * (sc.w + 1.f) + sh.w;
    ((float4*)g_h)[(size_t)row * 256 + tid] = h;
}

// ============================================================
// 3/6) SGEMM NT: C[M,N] = A[M,1024] * B[N,1024]^T  (+optional gate epilogue)
//      BM=BN=64, BK=16, 256 threads, 4x4 micro-tile.
//      mode 0: A=g_h,  C=g_qkv           (qkv projection)
//      mode 1: A=g_o,  C=Cext, *gate     (output projection)
// ============================================================
__global__ void __launch_bounds__(256) sgemm_kernel(const float* __restrict__ Bm,
                                                    float* __restrict__ Cext,
                                                    int N, int mode) {
    const int K = 1024;
    const float* A = mode ? g_o : g_h;
    float* C = mode ? Cext : g_qkv;

    __shared__ float As[16][64];
    __shared__ float Bs[16][64];

    int tid = threadIdx.x;
    int tx = tid & 15, ty = tid >> 4;
    int row0 = blockIdx.y * 64, col0 = blockIdx.x * 64;
    int lr = tid >> 2;            // 0..63
    int lk = (tid & 3) * 4;       // 0,4,8,12

    const float* Ap = A + (size_t)(row0 + lr) * K + lk;
    const float* Bp = Bm + (size_t)(col0 + lr) * K + lk;

    float acc[4][4] = {};

    for (int k0 = 0; k0 < K; k0 += 16) {
        float4 av = *(const float4*)(Ap + k0);
        float4 bv = *(const float4*)(Bp + k0);
        As[lk + 0][lr] = av.x; As[lk + 1][lr] = av.y;
        As[lk + 2][lr] = av.z; As[lk + 3][lr] = av.w;
        Bs[lk + 0][lr] = bv.x; Bs[lk + 1][lr] = bv.y;
        Bs[lk + 2][lr] = bv.z; Bs[lk + 3][lr] = bv.w;
        __syncthreads();
#pragma unroll
        for (int kk = 0; kk < 16; ++kk) {
            float4 a = ((const float4*)As[kk])[ty];
            float4 b4 = ((const float4*)Bs[kk])[tx];
            float av4[4] = {a.x, a.y, a.z, a.w};
            float bv4[4] = {b4.x, b4.y, b4.z, b4.w};
#pragma unroll
            for (int i = 0; i < 4; ++i)
#pragma unroll
                for (int j = 0; j < 4; ++j)
                    acc[i][j] = fmaf(av4[i], bv4[j], acc[i][j]);
        }
        __syncthreads();
    }

#pragma unroll
    for (int i = 0; i < 4; ++i) {
        int r = row0 + ty * 4 + i;
        int c = col0 + tx * 4;
        float4 v = make_float4(acc[i][0], acc[i][1], acc[i][2], acc[i][3]);
        if (mode) {
            const float* gp = g_mod + (r >> 11) * H3_ + 2 * H_ + c;
            v.x *= gp[0]; v.y *= gp[1]; v.z *= gp[2]; v.w *= gp[3];
        }
        *(float4*)(C + (size_t)r * N + c) = v;
    }
}

// ============================================================
// 4) per-head QK layernorm + RoPE, in place on g_qkv
//    one block per (b,s) row; warp-per-(head,q/k) tasks
// ============================================================
__global__ void __launch_bounds__(256) qknorm_rope_kernel(const float* __restrict__ freqs,
                                                          const float* __restrict__ qn_w,
                                                          const float* __restrict__ kn_w) {
    int row = blockIdx.x;            // 0..4095
    int s = row & (S_ - 1);
    int warp = threadIdx.x >> 5;
    int lane = threadIdx.x & 31;

    float f0 = freqs[(s * 32 + lane) * 2 + 0];
    float f1 = freqs[(s * 32 + lane) * 2 + 1];

    for (int task = warp; task < 32; task += 8) {
        int type = task >> 4;        // 0=q, 1=k
        int head = task & 15;
        size_t base = (size_t)row * H3_ + type * H_ + head * HD_;
        float v0 = g_qkv[base + lane * 2];
        float v1 = g_qkv[base + lane * 2 + 1];
        float sum = warp_sum(v0 + v1);
        float sq  = warp_sum(v0 * v0 + v1 * v1);
        float mean = sum * (1.f / 64.f);
        float var  = sq * (1.f / 64.f) - mean * mean;
        float rstd = rsqrtf(var + 1e-5f);
        const float* w = type ? kn_w : qn_w;
        float n0 = (v0 - mean) * rstd * w[lane * 2];
        float n1 = (v1 - mean) * rstd * w[lane * 2 + 1];
        g_qkv[base + lane * 2]     = n0 * f0 - n1 * f1;
        g_qkv[base + lane * 2 + 1] = n1 * f0 + n0 * f1;
    }
}

// ============================================================
// 5) flash attention (non-causal), fp32
//    grid = (S/64 qtiles, B*NH heads), 256 threads
//    BQ=64, BK=32; thread grid 16(ty q) x 16(tx), 4q x 2k scores, 4q x 4d output
// ============================================================
__global__ void __launch_bounds__(256) attn_kernel() {
    __shared__ float Qs[64 * 64];   // [d][q], pre-scaled by 1/8
    __shared__ float Ks[64 * 32];   // [d][k]
    __shared__ float Vs[32 * 64];   // [k][d]
    __shared__ float Ps[64 * 33];   // [q][k], padded

    int tid = threadIdx.x;
    int tx = tid & 15, ty = tid >> 4;
    int q0 = blockIdx.x * 64;
    int bh = blockIdx.y;
    int b = bh >> 4, head = bh & 15;

    const float* baseQ = g_qkv + (size_t)(b * S_ + q0) * H3_ + head * HD_;
    {
        int lr = tid >> 2;          // q row 0..63
        int lc = (tid & 3) * 4;
#pragma unroll
        for (int c = 0; c < 4; ++c) {
            int d = c * 16 + lc;
            float4 v = *(const float4*)(baseQ + (size_t)lr * H3_ + d);
            Qs[(d + 0) * 64 + lr] = v.x * 0.125f;
            Qs[(d + 1) * 64 + lr] = v.y * 0.125f;
            Qs[(d + 2) * 64 + lr] = v.z * 0.125f;
            Qs[(d + 3) * 64 + lr] = v.w * 0.125f;
        }
    }

    float m[4], l[4], o[4][4];
#pragma unroll
    for (int i = 0; i < 4; ++i) {
        m[i] = -1e30f; l[i] = 0.f;
#pragma unroll
        for (int j = 0; j < 4; ++j) o[i][j] = 0.f;
    }

    int lr2 = tid >> 3;             // key row 0..31
    int lc2 = (tid & 7) * 8;        // d chunk

    for (int s0 = 0; s0 < S_; s0 += 32) {
        __syncthreads();            // prior PV reads of Ks/Vs/Ps done
        const float* baseK = g_qkv + (size_t)(b * S_ + s0) * H3_ + H_ + head * HD_;
        const float* baseV = baseK + H_;
        {
            float4 k0 = *(const float4*)(baseK + (size_t)lr2 * H3_ + lc2);
            float4 k1 = *(const float4*)(baseK + (size_t)lr2 * H3_ + lc2 + 4);
            Ks[(lc2 + 0) * 32 + lr2] = k0.x;
            Ks[(lc2 + 1) * 32 + lr2] = k0.y;
            Ks[(lc2 + 2) * 32 + lr2] = k0.z;
            Ks[(lc2 + 3) * 32 + lr2] = k0.w;
            Ks[(lc2 + 4) * 32 + lr2] = k1.x;
            Ks[(lc2 + 5) * 32 + lr2] = k1.y;
            Ks[(lc2 + 6) * 32 + lr2] = k1.z;
            Ks[(lc2 + 7) * 32 + lr2] = k1.w;
            float4 v0 = *(const float4*)(baseV + (size_t)lr2 * H3_ + lc2);
            float4 v1 = *(const float4*)(baseV + (size_t)lr2 * H3_ + lc2 + 4);
            *(float4*)(Vs + lr2 * 64 + lc2)     = v0;
            *(float4*)(Vs + lr2 * 64 + lc2 + 4) = v1;
        }
        __syncthreads();

        // scores: 4q x 2k per thread over 64 dims
        float sc[4][2] = {};
#pragma unroll
        for (int d = 0; d < 64; ++d) {
            float4 a = *(const float4*)(Qs + d * 64 + ty * 4);
            float2 kb = *(const float2*)(Ks + d * 32 + tx * 2);
            float av4[4] = {a.x, a.y, a.z, a.w};
#pragma unroll
            for (int i = 0; i < 4; ++i) {
                sc[i][0] = fmaf(av4[i], kb.x, sc[i][0]);
                sc[i][1] = fmaf(av4[i], kb.y, sc[i][1]);
            }
        }

        // online softmax update (row reductions over tx lanes: bits 0..3)
#pragma unroll
        for (int i = 0; i < 4; ++i) {
            float tmax = fmaxf(sc[i][0], sc[i][1]);
#pragma unroll
            for (int off = 8; off; off >>= 1)
                tmax = fmaxf(tmax, __shfl_xor_sync(0xffffffffu, tmax, off));
            float nm = fmaxf(m[i], tmax);
            float alpha = __expf(m[i] - nm);
            m[i] = nm;
            float p0 = __expf(sc[i][0] - nm);
            float p1 = __expf(sc[i][1] - nm);
            Ps[(ty * 4 + i) * 33 + tx * 2 + 0] = p0;
            Ps[(ty * 4 + i) * 33 + tx * 2 + 1] = p1;
            float ps = p0 + p1;
#pragma unroll
            for (int off = 8; off; off >>= 1)
                ps += __shfl_xor_sync(0xffffffffu, ps, off);
            l[i] = l[i] * alpha + ps;
#pragma unroll
            for (int j = 0; j < 4; ++j) o[i][j] *= alpha;
        }
        __syncthreads();

        // O += P @ V
#pragma unroll 8
        for (int k = 0; k < 32; ++k) {
            float4 v = *(const float4*)(Vs + k * 64 + tx * 4);
#pragma unroll
            for (int i = 0; i < 4; ++i) {
                float p = Ps[(ty * 4 + i) * 33 + k];
                o[i][0] = fmaf(p, v.x, o[i][0]);
                o[i][1] = fmaf(p, v.y, o[i][1]);
                o[i][2] = fmaf(p, v.z, o[i][2]);
                o[i][3] = fmaf(p, v.w, o[i][3]);
            }
        }
    }

#pragma unroll
    for (int i = 0; i < 4; ++i) {
        float inv = 1.f / l[i];
        int row = b * S_ + q0 + ty * 4 + i;
        float4 out4 = make_float4(o[i][0] * inv, o[i][1] * inv,
                                  o[i][2] * inv, o[i][3] * inv);
        *(float4*)(g_o + (size_t)row * H_ + head * HD_ + tx * 4) = out4;
    }
}

// ============================================================
extern "C" void kernel_launch(void* const* d_in, const int* in_sizes, int n_in,
                              void* d_out, int out_size) {
    (void)in_sizes; (void)n_in; (void)out_size;
    const float* x     = (const float*)d_in[0];
    const float* ada   = (const float*)d_in[1];
    const float* freqs = (const float*)d_in[2];
    const float* w_qkv = (const float*)d_in[3];
    const float* w_o   = (const float*)d_in[4];
    const float* ln_w  = (const float*)d_in[5];
    const float* mod_w = (const float*)d_in[6];
    const float* mod_b = (const float*)d_in[7];
    const float* qn_w  = (const float*)d_in[8];
    const float* kn_w  = (const float*)d_in[9];
    float* out = (float*)d_out;

    mod_kernel<<<768, 256>>>(ada, mod_w, mod_b);                       // 6144 warps
    ln_mod_kernel<<<R_, 256>>>(x, ln_w);
    sgemm_kernel<<<dim3(H3_ / 64, R_ / 64), 256>>>(w_qkv, nullptr, H3_, 0);
    qknorm_rope_kernel<<<R_, 256>>>(freqs, qn_w, kn_w);
    attn_kernel<<<dim3(S_ / 64, B_ * NH_), 256>>>();
    sgemm_kernel<<<dim3(H_ / 64, R_ / 64), 256>>>(w_o, out, H_, 1);
}

// round 5
// speedup vs baseline: 1.5124x; 1.5122x over previous
#include <cuda_runtime.h>
#include <cstdint>
#include <math.h>

#define B_ 2
#define S_ 2048
#define H_ 1024
#define NH_ 16
#define HD_ 64
#define H3_ 3072
#define R_ 4096   // B*S

// ---- scratch (static device globals; no runtime allocation) ----
__device__ __align__(256) float g_mod[B_ * H3_];           // [B, 3H] (scale|shift|gate)
__device__ __align__(256) float g_h[(size_t)R_ * H_];      // modulated LN output (tf32-rounded)
__device__ __align__(256) float g_qkv[(size_t)R_ * H3_];   // qkv projections
__device__ __align__(256) float g_o[(size_t)R_ * H_];      // attention output (tf32-rounded)
__device__ __align__(256) float g_w1[(size_t)H3_ * H_];    // tf32-rounded w_qkv
__device__ __align__(256) float g_w2[(size_t)H_ * H_];     // tf32-rounded w_o

// ============================================================
// helpers
// ============================================================
__device__ __forceinline__ float warp_sum(float v) {
#pragma unroll
    for (int o = 16; o; o >>= 1) v += __shfl_xor_sync(0xffffffffu, v, o);
    return v;
}

__device__ __forceinline__ float to_tf32(float x) {
    float r;
    asm("cvt.rna.tf32.f32 %0, %1;" : "=f"(r) : "f"(x));
    return r;
}

__device__ __forceinline__ uint32_t cvta_smem(const void* p) {
    uint32_t a;
    asm("{ .reg .u64 t; cvta.to.shared.u64 t, %1; cvt.u32.u64 %0, t; }" : "=r"(a) : "l"(p));
    return a;
}

__device__ __forceinline__ void cp_async16(uint32_t dst, const void* src) {
    asm volatile("cp.async.cg.shared.global [%0], [%1], 16;" :: "r"(dst), "l"(src));
}

// mma.sync tf32: D[16x8] += A[16x8] * B[8x8]   (portable, sm_80+)
__device__ __forceinline__ void mma1688(float* d, const uint32_t* a, uint32_t b0, uint32_t b1) {
    asm volatile(
        "mma.sync.aligned.m16n8k8.row.col.f32.tf32.tf32.f32 "
        "{%0,%1,%2,%3}, {%4,%5,%6,%7}, {%8,%9}, {%0,%1,%2,%3};"
        : "+f"(d[0]), "+f"(d[1]), "+f"(d[2]), "+f"(d[3])
        : "r"(a[0]), "r"(a[1]), "r"(a[2]), "r"(a[3]), "r"(b0), "r"(b1));
}

// ============================================================
// 0) round weights fp32 -> tf32 (RNA)
// ============================================================
__global__ void __launch_bounds__(256) round_w_kernel(const float* __restrict__ wq,
                                                      const float* __restrict__ wo) {
    const size_t n1 = (size_t)H3_ * H_ / 4;
    const size_t n2 = (size_t)H_ * H_ / 4;
    size_t i = (size_t)blockIdx.x * 256 + threadIdx.x;
    if (i < n1) {
        float4 v = ((const float4*)wq)[i];
        v.x = to_tf32(v.x); v.y = to_tf32(v.y); v.z = to_tf32(v.z); v.w = to_tf32(v.w);
        ((float4*)g_w1)[i] = v;
    } else if (i < n1 + n2) {
        size_t j = i - n1;
        float4 v = ((const float4*)wo)[j];
        v.x = to_tf32(v.x); v.y = to_tf32(v.y); v.z = to_tf32(v.z); v.w = to_tf32(v.w);
        ((float4*)g_w2)[j] = v;
    }
}

// ============================================================
// 1) mod = silu(ada) @ mod_w^T + mod_b       (one warp per output)
// ============================================================
__global__ void __launch_bounds__(256) mod_kernel(const float* __restrict__ ada,
                                                  const float* __restrict__ mw,
                                                  const float* __restrict__ mb) {
    int gw = (blockIdx.x * 256 + threadIdx.x) >> 5;
    int lane = threadIdx.x & 31;
    int b = gw / H3_, j = gw % H3_;
    const float* ar = ada + b * 1024;
    const float* wr = mw + (size_t)j * 1024;
    float acc = 0.f;
#pragma unroll 4
    for (int a = lane; a < 1024; a += 32) {
        float v = ar[a];
        float s = v / (1.f + __expf(-v));
        acc = fmaf(s, wr[a], acc);
    }
    acc = warp_sum(acc);
    if (lane == 0) g_mod[gw] = acc + mb[j];
}

// ============================================================
// 2) h = LN(x)*ln_w*(scale+1) + shift   (tf32-rounded for GEMM A)
// ============================================================
__global__ void __launch_bounds__(256) ln_mod_kernel(const float* __restrict__ x,
                                                     const float* __restrict__ ln_w) {
    int row = blockIdx.x;
    int tid = threadIdx.x;
    int b = row >> 11;

    float4 xv = ((const float4*)x)[(size_t)row * 256 + tid];
    float sum = xv.x + xv.y + xv.z + xv.w;
    float sq  = xv.x * xv.x + xv.y * xv.y + xv.z * xv.z + xv.w * xv.w;
    sum = warp_sum(sum);
    sq  = warp_sum(sq);

    __shared__ float rs[8], rq[8], mv[2];
    int warp = tid >> 5, lane = tid & 31;
    if (lane == 0) { rs[warp] = sum; rq[warp] = sq; }
    __syncthreads();
    if (tid == 0) {
        float s = 0.f, q = 0.f;
#pragma unroll
        for (int w = 0; w < 8; ++w) { s += rs[w]; q += rq[w]; }
        float mean = s * (1.f / 1024.f);
        float var  = q * (1.f / 1024.f) - mean * mean;
        mv[0] = mean;
        mv[1] = rsqrtf(var + 1e-5f);
    }
    __syncthreads();
    float mean = mv[0], rstd = mv[1];

    float4 lw = ((const float4*)ln_w)[tid];
    const float* mp = g_mod + b * H3_;
    float4 sc = ((const float4*)mp)[tid];
    float4 sh = ((const float4*)(mp + H_))[tid];

    float4 h;
    h.x = to_tf32((xv.x - mean) * rstd * lw.x * (sc.x + 1.f) + sh.x);
    h.y = to_tf32((xv.y - mean) * rstd * lw.y * (sc.y + 1.f) + sh.y);
    h.z = to_tf32((xv.z - mean) * rstd * lw.z * (sc.z + 1.f) + sh.z);
    h.w = to_tf32((xv.w - mean) * rstd * lw.w * (sc.w + 1.f) + sh.w);
    ((float4*)g_h)[(size_t)row * 256 + tid] = h;
}

// ============================================================
// 3/6) tf32 mma.sync GEMM NT: C[M,N] = A[M,1024] * B[N,1024]^T
//      128x128 CTA tile, BK=16, 4-stage cp.async, 8 warps (32x64 each).
//      Smem tiles stored [row][k] with stride 20 floats (pad -> conflict-free).
//      mode 0: A=g_h,  B=g_w1, C=g_qkv          (qkv projection)
//      mode 1: A=g_o,  B=g_w2, C=Cext, *gate    (output projection)
// ============================================================
#define GK_ 1024
#define GNIT 64                 // GK_/16
#define STG_FLOATS 5120         // per stage: A(2560) + B(2560)
#define STG_BYTES  20480

__device__ __forceinline__ void gemm_load_stage(uint32_t sb, const float* A, const float* Bm,
                                                int row0, int col0, int it, int tid) {
    int s = it & 3;
    int krow = it * 16;
    int r = tid >> 1;                 // 0..127
    int off = (tid & 1) * 8;          // 0 or 8 floats
    uint32_t base = sb + s * STG_BYTES;
    const float* ga = A + (size_t)(row0 + r) * GK_ + krow + off;
    uint32_t da = base + (r * 20 + off) * 4;
    cp_async16(da, ga);
    cp_async16(da + 16, ga + 4);
    const float* gb = Bm + (size_t)(col0 + r) * GK_ + krow + off;
    uint32_t db = base + 10240 + (r * 20 + off) * 4;
    cp_async16(db, gb);
    cp_async16(db + 16, gb + 4);
    asm volatile("cp.async.commit_group;" ::: "memory");
}

__global__ void __launch_bounds__(256, 1) tc_gemm(float* __restrict__ Cext, int N, int mode) {
    extern __shared__ float sm[];
    const float* A  = mode ? g_o : g_h;
    const float* Bm = mode ? g_w2 : g_w1;
    float* C = mode ? Cext : g_qkv;

    uint32_t sb = cvta_smem(sm);
    int tid = threadIdx.x;
    int wid = tid >> 5, lane = tid & 31;
    int warp_m = wid & 3, warp_n = wid >> 2;
    int row0 = blockIdx.y << 7, col0 = blockIdx.x << 7;

    int lr = lane >> 2;      // 0..7
    int lk = lane & 3;       // 0..3

    float acc[2][8][4];
#pragma unroll
    for (int i = 0; i < 2; ++i)
#pragma unroll
        for (int j = 0; j < 8; ++j)
#pragma unroll
            for (int q = 0; q < 4; ++q) acc[i][j][q] = 0.f;

    gemm_load_stage(sb, A, Bm, row0, col0, 0, tid);
    gemm_load_stage(sb, A, Bm, row0, col0, 1, tid);
    gemm_load_stage(sb, A, Bm, row0, col0, 2, tid);

    for (int it = 0; it < GNIT; ++it) {
        asm volatile("cp.async.wait_group 2;" ::: "memory");
        __syncthreads();

        const float* As = sm + (it & 3) * STG_FLOATS;
        const float* Bs = As + 2560;
#pragma unroll
        for (int k8 = 0; k8 < 16; k8 += 8) {
            uint32_t a[2][4];
#pragma unroll
            for (int mt = 0; mt < 2; ++mt) {
                int rb = (warp_m * 32 + mt * 16 + lr) * 20 + k8 + lk;
                a[mt][0] = __float_as_uint(As[rb]);
                a[mt][1] = __float_as_uint(As[rb + 8 * 20]);
                a[mt][2] = __float_as_uint(As[rb + 4]);
                a[mt][3] = __float_as_uint(As[rb + 8 * 20 + 4]);
            }
#pragma unroll
            for (int nt = 0; nt < 8; ++nt) {
                int nb = (warp_n * 64 + nt * 8 + lr) * 20 + k8 + lk;
                uint32_t b0 = __float_as_uint(Bs[nb]);
                uint32_t b1 = __float_as_uint(Bs[nb + 4]);
                mma1688(acc[0][nt], a[0], b0, b1);
                mma1688(acc[1][nt], a[1], b0, b1);
            }
        }
        __syncthreads();
        if (it + 3 < GNIT) gemm_load_stage(sb, A, Bm, row0, col0, it + 3, tid);
    }

    // epilogue: direct global stores (float2 per fragment row)
#pragma unroll
    for (int mt = 0; mt < 2; ++mt) {
        int r = row0 + warp_m * 32 + mt * 16 + lr;
        int gb = (r >> 11) * H3_ + 2 * H_;       // gate base for this row's batch
#pragma unroll
        for (int nt = 0; nt < 8; ++nt) {
            int c = col0 + warp_n * 64 + nt * 8 + lk * 2;
            float2 v0 = make_float2(acc[mt][nt][0], acc[mt][nt][1]);
            float2 v1 = make_float2(acc[mt][nt][2], acc[mt][nt][3]);
            if (mode) {
                float gx = g_mod[gb + c], gy = g_mod[gb + c + 1];
                v0.x *= gx; v0.y *= gy;
                v1.x *= gx; v1.y *= gy;
            }
            *(float2*)(C + (size_t)r * N + c) = v0;
            *(float2*)(C + (size_t)(r + 8) * N + c) = v1;
        }
    }
}

// ============================================================
// 4) per-head QK layernorm + RoPE, in place on g_qkv
// ============================================================
__global__ void __launch_bounds__(256) qknorm_rope_kernel(const float* __restrict__ freqs,
                                                          const float* __restrict__ qn_w,
                                                          const float* __restrict__ kn_w) {
    int row = blockIdx.x;
    int s = row & (S_ - 1);
    int warp = threadIdx.x >> 5;
    int lane = threadIdx.x & 31;

    float f0 = freqs[(s * 32 + lane) * 2 + 0];
    float f1 = freqs[(s * 32 + lane) * 2 + 1];

    for (int task = warp; task < 32; task += 8) {
        int type = task >> 4;
        int head = task & 15;
        size_t base = (size_t)row * H3_ + type * H_ + head * HD_;
        float v0 = g_qkv[base + lane * 2];
        float v1 = g_qkv[base + lane * 2 + 1];
        float sum = warp_sum(v0 + v1);
        float sq  = warp_sum(v0 * v0 + v1 * v1);
        float mean = sum * (1.f / 64.f);
        float var  = sq * (1.f / 64.f) - mean * mean;
        float rstd = rsqrtf(var + 1e-5f);
        const float* w = type ? kn_w : qn_w;
        float n0 = (v0 - mean) * rstd * w[lane * 2];
        float n1 = (v1 - mean) * rstd * w[lane * 2 + 1];
        g_qkv[base + lane * 2]     = n0 * f0 - n1 * f1;
        g_qkv[base + lane * 2 + 1] = n1 * f0 + n0 * f1;
    }
}

// ============================================================
// 5) flash attention (non-causal), fp32 FFMA (tf32-rounded output)
// ============================================================
__global__ void __launch_bounds__(256) attn_kernel() {
    __shared__ float Qs[64 * 64];
    __shared__ float Ks[64 * 32];
    __shared__ float Vs[32 * 64];
    __shared__ float Ps[64 * 33];

    int tid = threadIdx.x;
    int tx = tid & 15, ty = tid >> 4;
    int q0 = blockIdx.x * 64;
    int bh = blockIdx.y;
    int b = bh >> 4, head = bh & 15;

    const float* baseQ = g_qkv + (size_t)(b * S_ + q0) * H3_ + head * HD_;
    {
        int lr = tid >> 2;
        int lc = (tid & 3) * 4;
#pragma unroll
        for (int cc = 0; cc < 4; ++cc) {
            int d = cc * 16 + lc;
            float4 v = *(const float4*)(baseQ + (size_t)lr * H3_ + d);
            Qs[(d + 0) * 64 + lr] = v.x * 0.125f;
            Qs[(d + 1) * 64 + lr] = v.y * 0.125f;
            Qs[(d + 2) * 64 + lr] = v.z * 0.125f;
            Qs[(d + 3) * 64 + lr] = v.w * 0.125f;
        }
    }

    float m[4], l[4], o[4][4];
#pragma unroll
    for (int i = 0; i < 4; ++i) {
        m[i] = -1e30f; l[i] = 0.f;
#pragma unroll
        for (int j = 0; j < 4; ++j) o[i][j] = 0.f;
    }

    int lr2 = tid >> 3;
    int lc2 = (tid & 7) * 8;

    for (int s0 = 0; s0 < S_; s0 += 32) {
        __syncthreads();
        const float* baseK = g_qkv + (size_t)(b * S_ + s0) * H3_ + H_ + head * HD_;
        const float* baseV = baseK + H_;
        {
            float4 k0 = *(const float4*)(baseK + (size_t)lr2 * H3_ + lc2);
            float4 k1 = *(const float4*)(baseK + (size_t)lr2 * H3_ + lc2 + 4);
            Ks[(lc2 + 0) * 32 + lr2] = k0.x;
            Ks[(lc2 + 1) * 32 + lr2] = k0.y;
            Ks[(lc2 + 2) * 32 + lr2] = k0.z;
            Ks[(lc2 + 3) * 32 + lr2] = k0.w;
            Ks[(lc2 + 4) * 32 + lr2] = k1.x;
            Ks[(lc2 + 5) * 32 + lr2] = k1.y;
            Ks[(lc2 + 6) * 32 + lr2] = k1.z;
            Ks[(lc2 + 7) * 32 + lr2] = k1.w;
            float4 v0 = *(const float4*)(baseV + (size_t)lr2 * H3_ + lc2);
            float4 v1 = *(const float4*)(baseV + (size_t)lr2 * H3_ + lc2 + 4);
            *(float4*)(Vs + lr2 * 64 + lc2)     = v0;
            *(float4*)(Vs + lr2 * 64 + lc2 + 4) = v1;
        }
        __syncthreads();

        float sc[4][2] = {};
#pragma unroll
        for (int d = 0; d < 64; ++d) {
            float4 a = *(const float4*)(Qs + d * 64 + ty * 4);
            float2 kb = *(const float2*)(Ks + d * 32 + tx * 2);
            float av4[4] = {a.x, a.y, a.z, a.w};
#pragma unroll
            for (int i = 0; i < 4; ++i) {
                sc[i][0] = fmaf(av4[i], kb.x, sc[i][0]);
                sc[i][1] = fmaf(av4[i], kb.y, sc[i][1]);
            }
        }

#pragma unroll
        for (int i = 0; i < 4; ++i) {
            float tmax = fmaxf(sc[i][0], sc[i][1]);
#pragma unroll
            for (int off = 8; off; off >>= 1)
                tmax = fmaxf(tmax, __shfl_xor_sync(0xffffffffu, tmax, off));
            float nm = fmaxf(m[i], tmax);
            float alpha = __expf(m[i] - nm);
            m[i] = nm;
            float p0 = __expf(sc[i][0] - nm);
            float p1 = __expf(sc[i][1] - nm);
            Ps[(ty * 4 + i) * 33 + tx * 2 + 0] = p0;
            Ps[(ty * 4 + i) * 33 + tx * 2 + 1] = p1;
            float ps = p0 + p1;
#pragma unroll
            for (int off = 8; off; off >>= 1)
                ps += __shfl_xor_sync(0xffffffffu, ps, off);
            l[i] = l[i] * alpha + ps;
#pragma unroll
            for (int j = 0; j < 4; ++j) o[i][j] *= alpha;
        }
        __syncthreads();

#pragma unroll 8
        for (int k = 0; k < 32; ++k) {
            float4 v = *(const float4*)(Vs + k * 64 + tx * 4);
#pragma unroll
            for (int i = 0; i < 4; ++i) {
                float p = Ps[(ty * 4 + i) * 33 + k];
                o[i][0] = fmaf(p, v.x, o[i][0]);
                o[i][1] = fmaf(p, v.y, o[i][1]);
                o[i][2] = fmaf(p, v.z, o[i][2]);
                o[i][3] = fmaf(p, v.w, o[i][3]);
            }
        }
    }

#pragma unroll
    for (int i = 0; i < 4; ++i) {
        float inv = 1.f / l[i];
        int row = b * S_ + q0 + ty * 4 + i;
        float4 out4 = make_float4(to_tf32(o[i][0] * inv), to_tf32(o[i][1] * inv),
                                  to_tf32(o[i][2] * inv), to_tf32(o[i][3] * inv));
        *(float4*)(g_o + (size_t)row * H_ + head * HD_ + tx * 4) = out4;
    }
}

// ============================================================
extern "C" void kernel_launch(void* const* d_in, const int* in_sizes, int n_in,
                              void* d_out, int out_size) {
    (void)in_sizes; (void)n_in; (void)out_size;
    const float* x     = (const float*)d_in[0];
    const float* ada   = (const float*)d_in[1];
    const float* freqs = (const float*)d_in[2];
    const float* w_qkv = (const float*)d_in[3];
    const float* w_o   = (const float*)d_in[4];
    const float* ln_w  = (const float*)d_in[5];
    const float* mod_w = (const float*)d_in[6];
    const float* mod_b = (const float*)d_in[7];
    const float* qn_w  = (const float*)d_in[8];
    const float* kn_w  = (const float*)d_in[9];
    float* out = (float*)d_out;

    const int SMEM_DYN = 4 * STG_BYTES;   // 81920 bytes
    cudaFuncSetAttribute(tc_gemm, cudaFuncAttributeMaxDynamicSharedMemorySize, SMEM_DYN);

    mod_kernel<<<768, 256>>>(ada, mod_w, mod_b);
    round_w_kernel<<<4096, 256>>>(w_qkv, w_o);
    ln_mod_kernel<<<R_, 256>>>(x, ln_w);
    tc_gemm<<<dim3(H3_ / 128, R_ / 128), 256, SMEM_DYN>>>(nullptr, H3_, 0);
    qknorm_rope_kernel<<<R_, 256>>>(freqs, qn_w, kn_w);
    attn_kernel<<<dim3(S_ / 64, B_ * NH_), 256>>>();
    tc_gemm<<<dim3(H_ / 128, R_ / 128), 256, SMEM_DYN>>>(out, H_, 1);
}

// round 9
// speedup vs baseline: 2.8106x; 1.8584x over previous
#include <cuda_runtime.h>
#include <cstdint>
#include <math.h>

#define B_ 2
#define S_ 2048
#define H_ 1024
#define NH_ 16
#define HD_ 64
#define H3_ 3072
#define R_ 4096   // B*S

// ---- scratch (static device globals; no runtime allocation) ----
__device__ __align__(256) float g_mod[B_ * H3_];           // [B, 3H] (scale|shift|gate)
__device__ __align__(256) float g_h[(size_t)R_ * H_];      // modulated LN output (tf32-rounded)
__device__ __align__(256) float g_qkv[(size_t)R_ * H3_];   // qkv projections (tf32-rounded)
__device__ __align__(256) float g_o[(size_t)R_ * H_];      // attention output (tf32-rounded)
__device__ __align__(256) float g_w1[(size_t)H3_ * H_];    // tf32-rounded w_qkv
__device__ __align__(256) float g_w2[(size_t)H_ * H_];     // tf32-rounded w_o

// ============================================================
// helpers
// ============================================================
__device__ __forceinline__ float warp_sum(float v) {
#pragma unroll
    for (int o = 16; o; o >>= 1) v += __shfl_xor_sync(0xffffffffu, v, o);
    return v;
}

__device__ __forceinline__ float to_tf32(float x) {
    float r;
    asm("cvt.rna.tf32.f32 %0, %1;" : "=f"(r) : "f"(x));
    return r;
}

__device__ __forceinline__ uint32_t cvta_smem(const void* p) {
    uint32_t a;
    asm("{ .reg .u64 t; cvta.to.shared.u64 t, %1; cvt.u32.u64 %0, t; }" : "=r"(a) : "l"(p));
    return a;
}

__device__ __forceinline__ void cp_async16(uint32_t dst, const void* src) {
    asm volatile("cp.async.cg.shared.global [%0], [%1], 16;" :: "r"(dst), "l"(src));
}

// mma.sync tf32: D[16x8] += A[16x8] * B[8x8]   (portable, sm_80+)
__device__ __forceinline__ void mma1688(float* d, const uint32_t* a, uint32_t b0, uint32_t b1) {
    asm volatile(
        "mma.sync.aligned.m16n8k8.row.col.f32.tf32.tf32.f32 "
        "{%0,%1,%2,%3}, {%4,%5,%6,%7}, {%8,%9}, {%0,%1,%2,%3};"
        : "+f"(d[0]), "+f"(d[1]), "+f"(d[2]), "+f"(d[3])
        : "r"(a[0]), "r"(a[1]), "r"(a[2]), "r"(a[3]), "r"(b0), "r"(b1));
}

// ============================================================
// 0) round weights fp32 -> tf32 (RNA)
// ============================================================
__global__ void __launch_bounds__(256) round_w_kernel(const float* __restrict__ wq,
                                                      const float* __restrict__ wo) {
    const size_t n1 = (size_t)H3_ * H_ / 4;
    const size_t n2 = (size_t)H_ * H_ / 4;
    size_t i = (size_t)blockIdx.x * 256 + threadIdx.x;
    if (i < n1) {
        float4 v = ((const float4*)wq)[i];
        v.x = to_tf32(v.x); v.y = to_tf32(v.y); v.z = to_tf32(v.z); v.w = to_tf32(v.w);
        ((float4*)g_w1)[i] = v;
    } else if (i < n1 + n2) {
        size_t j = i - n1;
        float4 v = ((const float4*)wo)[j];
        v.x = to_tf32(v.x); v.y = to_tf32(v.y); v.z = to_tf32(v.z); v.w = to_tf32(v.w);
        ((float4*)g_w2)[j] = v;
    }
}

// ============================================================
// 1) mod = silu(ada) @ mod_w^T + mod_b       (one warp per output)
// ============================================================
__global__ void __launch_bounds__(256) mod_kernel(const float* __restrict__ ada,
                                                  const float* __restrict__ mw,
                                                  const float* __restrict__ mb) {
    int gw = (blockIdx.x * 256 + threadIdx.x) >> 5;
    int lane = threadIdx.x & 31;
    int b = gw / H3_, j = gw % H3_;
    const float* ar = ada + b * 1024;
    const float* wr = mw + (size_t)j * 1024;
    float acc = 0.f;
#pragma unroll 4
    for (int a = lane; a < 1024; a += 32) {
        float v = ar[a];
        float s = v / (1.f + __expf(-v));
        acc = fmaf(s, wr[a], acc);
    }
    acc = warp_sum(acc);
    if (lane == 0) g_mod[gw] = acc + mb[j];
}

// ============================================================
// 2) h = LN(x)*ln_w*(scale+1) + shift   (tf32-rounded for GEMM A)
// ============================================================
__global__ void __launch_bounds__(256) ln_mod_kernel(const float* __restrict__ x,
                                                     const float* __restrict__ ln_w) {
    int row = blockIdx.x;
    int tid = threadIdx.x;
    int b = row >> 11;

    float4 xv = ((const float4*)x)[(size_t)row * 256 + tid];
    float sum = xv.x + xv.y + xv.z + xv.w;
    float sq  = xv.x * xv.x + xv.y * xv.y + xv.z * xv.z + xv.w * xv.w;
    sum = warp_sum(sum);
    sq  = warp_sum(sq);

    __shared__ float rs[8], rq[8], mv[2];
    int warp = tid >> 5, lane = tid & 31;
    if (lane == 0) { rs[warp] = sum; rq[warp] = sq; }
    __syncthreads();
    if (tid == 0) {
        float s = 0.f, q = 0.f;
#pragma unroll
        for (int w = 0; w < 8; ++w) { s += rs[w]; q += rq[w]; }
        float mean = s * (1.f / 1024.f);
        float var  = q * (1.f / 1024.f) - mean * mean;
        mv[0] = mean;
        mv[1] = rsqrtf(var + 1e-5f);
    }
    __syncthreads();
    float mean = mv[0], rstd = mv[1];

    float4 lw = ((const float4*)ln_w)[tid];
    const float* mp = g_mod + b * H3_;
    float4 sc = ((const float4*)mp)[tid];
    float4 sh = ((const float4*)(mp + H_))[tid];

    float4 h;
    h.x = to_tf32((xv.x - mean) * rstd * lw.x * (sc.x + 1.f) + sh.x);
    h.y = to_tf32((xv.y - mean) * rstd * lw.y * (sc.y + 1.f) + sh.y);
    h.z = to_tf32((xv.z - mean) * rstd * lw.z * (sc.z + 1.f) + sh.z);
    h.w = to_tf32((xv.w - mean) * rstd * lw.w * (sc.w + 1.f) + sh.w);
    ((float4*)g_h)[(size_t)row * 256 + tid] = h;
}

// ============================================================
// 3/6) tf32 mma.sync GEMM NT: C[M,N] = A[M,1024] * B[N,1024]^T
// ============================================================
#define GK_ 1024
#define GNIT 64                 // GK_/16
#define STG_FLOATS 5120         // per stage: A(2560) + B(2560)
#define STG_BYTES  20480

__device__ __forceinline__ void gemm_load_stage(uint32_t sb, const float* A, const float* Bm,
                                                int row0, int col0, int it, int tid) {
    int s = it & 3;
    int krow = it * 16;
    int r = tid >> 1;                 // 0..127
    int off = (tid & 1) * 8;          // 0 or 8 floats
    uint32_t base = sb + s * STG_BYTES;
    const float* ga = A + (size_t)(row0 + r) * GK_ + krow + off;
    uint32_t da = base + (r * 20 + off) * 4;
    cp_async16(da, ga);
    cp_async16(da + 16, ga + 4);
    const float* gb = Bm + (size_t)(col0 + r) * GK_ + krow + off;
    uint32_t db = base + 10240 + (r * 20 + off) * 4;
    cp_async16(db, gb);
    cp_async16(db + 16, gb + 4);
    asm volatile("cp.async.commit_group;" ::: "memory");
}

__global__ void __launch_bounds__(256, 1) tc_gemm(float* __restrict__ Cext, int N, int mode) {
    extern __shared__ float sm[];
    const float* A  = mode ? g_o : g_h;
    const float* Bm = mode ? g_w2 : g_w1;
    float* C = mode ? Cext : g_qkv;

    uint32_t sb = cvta_smem(sm);
    int tid = threadIdx.x;
    int wid = tid >> 5, lane = tid & 31;
    int warp_m = wid & 3, warp_n = wid >> 2;
    int row0 = blockIdx.y << 7, col0 = blockIdx.x << 7;

    int lr = lane >> 2;      // 0..7
    int lk = lane & 3;       // 0..3

    float acc[2][8][4];
#pragma unroll
    for (int i = 0; i < 2; ++i)
#pragma unroll
        for (int j = 0; j < 8; ++j)
#pragma unroll
            for (int q = 0; q < 4; ++q) acc[i][j][q] = 0.f;

    gemm_load_stage(sb, A, Bm, row0, col0, 0, tid);
    gemm_load_stage(sb, A, Bm, row0, col0, 1, tid);
    gemm_load_stage(sb, A, Bm, row0, col0, 2, tid);

    for (int it = 0; it < GNIT; ++it) {
        asm volatile("cp.async.wait_group 2;" ::: "memory");
        __syncthreads();

        const float* As = sm + (it & 3) * STG_FLOATS;
        const float* Bs = As + 2560;
#pragma unroll
        for (int k8 = 0; k8 < 16; k8 += 8) {
            uint32_t a[2][4];
#pragma unroll
            for (int mt = 0; mt < 2; ++mt) {
                int rb = (warp_m * 32 + mt * 16 + lr) * 20 + k8 + lk;
                a[mt][0] = __float_as_uint(As[rb]);
                a[mt][1] = __float_as_uint(As[rb + 8 * 20]);
                a[mt][2] = __float_as_uint(As[rb + 4]);
                a[mt][3] = __float_as_uint(As[rb + 8 * 20 + 4]);
            }
#pragma unroll
            for (int nt = 0; nt < 8; ++nt) {
                int nb = (warp_n * 64 + nt * 8 + lr) * 20 + k8 + lk;
                uint32_t b0 = __float_as_uint(Bs[nb]);
                uint32_t b1 = __float_as_uint(Bs[nb + 4]);
                mma1688(acc[0][nt], a[0], b0, b1);
                mma1688(acc[1][nt], a[1], b0, b1);
            }
        }
        __syncthreads();
        if (it + 3 < GNIT) gemm_load_stage(sb, A, Bm, row0, col0, it + 3, tid);
    }

    // epilogue (mode 0: round to tf32 for attention consumers; mode 1: gate)
#pragma unroll
    for (int mt = 0; mt < 2; ++mt) {
        int r = row0 + warp_m * 32 + mt * 16 + lr;
        int gb = (r >> 11) * H3_ + 2 * H_;
#pragma unroll
        for (int nt = 0; nt < 8; ++nt) {
            int c = col0 + warp_n * 64 + nt * 8 + lk * 2;
            float2 v0 = make_float2(acc[mt][nt][0], acc[mt][nt][1]);
            float2 v1 = make_float2(acc[mt][nt][2], acc[mt][nt][3]);
            if (mode) {
                float gx = g_mod[gb + c], gy = g_mod[gb + c + 1];
                v0.x *= gx; v0.y *= gy;
                v1.x *= gx; v1.y *= gy;
            } else {
                v0.x = to_tf32(v0.x); v0.y = to_tf32(v0.y);
                v1.x = to_tf32(v1.x); v1.y = to_tf32(v1.y);
            }
            *(float2*)(C + (size_t)r * N + c) = v0;
            *(float2*)(C + (size_t)(r + 8) * N + c) = v1;
        }
    }
}

// ============================================================
// 4) per-head QK layernorm + RoPE, in place on g_qkv
//    q gets the 1/sqrt(hd)=0.125 attention scale folded in; outputs tf32-rounded
// ============================================================
__global__ void __launch_bounds__(256) qknorm_rope_kernel(const float* __restrict__ freqs,
                                                          const float* __restrict__ qn_w,
                                                          const float* __restrict__ kn_w) {
    int row = blockIdx.x;
    int s = row & (S_ - 1);
    int warp = threadIdx.x >> 5;
    int lane = threadIdx.x & 31;

    float f0 = freqs[(s * 32 + lane) * 2 + 0];
    float f1 = freqs[(s * 32 + lane) * 2 + 1];

    for (int task = warp; task < 32; task += 8) {
        int type = task >> 4;
        int head = task & 15;
        size_t base = (size_t)row * H3_ + type * H_ + head * HD_;
        float v0 = g_qkv[base + lane * 2];
        float v1 = g_qkv[base + lane * 2 + 1];
        float sum = warp_sum(v0 + v1);
        float sq  = warp_sum(v0 * v0 + v1 * v1);
        float mean = sum * (1.f / 64.f);
        float var  = sq * (1.f / 64.f) - mean * mean;
        float rstd = rsqrtf(var + 1e-5f);
        const float* w = type ? kn_w : qn_w;
        float n0 = (v0 - mean) * rstd * w[lane * 2];
        float n1 = (v1 - mean) * rstd * w[lane * 2 + 1];
        float r0 = n0 * f0 - n1 * f1;
        float r1 = n1 * f0 + n0 * f1;
        float qs = type ? 1.f : 0.125f;
        g_qkv[base + lane * 2]     = to_tf32(r0 * qs);
        g_qkv[base + lane * 2 + 1] = to_tf32(r1 * qs);
    }
}

// ============================================================
// 5) flash attention (non-causal), tf32 mma.sync
//    grid = (S/128, B*NH), 256 threads (8 warps x m16 q-rows)
//    K/V 64-key tiles double-buffered (stride 72), P staged per-warp (stride 68)
// ============================================================
#define KVS 72
#define PS_ 68
#define ATT_SMEM ((4 * 64 * KVS + 8 * 16 * PS_) * 4)   // 108544 bytes

__device__ __forceinline__ void attn_load_kv(uint32_t sb, const float* gkv, int t, int tid) {
    int s = t & 1;
    int r = tid >> 2;                 // 0..63 (key within tile)
    int cc = (tid & 3) * 16;          // dim chunk
    const float* kg = gkv + (size_t)(t * 64 + r) * H3_ + cc;
    uint32_t kd = sb + (s * 64 * KVS + r * KVS + cc) * 4;
    uint32_t vd = kd + 2 * 64 * KVS * 4;
    const float* vg = kg + H_;
#pragma unroll
    for (int i = 0; i < 4; ++i) {
        cp_async16(kd + i * 16, kg + i * 4);
        cp_async16(vd + i * 16, vg + i * 4);
    }
    asm volatile("cp.async.commit_group;" ::: "memory");
}

__global__ void __launch_bounds__(256, 1) attn_mma_kernel() {
    extern __shared__ float sm[];
    uint32_t sb = cvta_smem(sm);
    float* Ks = sm;                        // [2][64][KVS]
    float* Vs = sm + 2 * 64 * KVS;         // [2][64][KVS]
    float* Ps = sm + 4 * 64 * KVS;         // [8][16][PS_]

    int tid = threadIdx.x, wid = tid >> 5, lane = tid & 31;
    int lr = lane >> 2, lk = lane & 3;
    int q0 = blockIdx.x << 7;
    int b = blockIdx.y >> 4, head = blockIdx.y & 15;

    const float* gkv = g_qkv + (size_t)b * S_ * H3_ + H_ + head * HD_;  // K base (V = +H_)

    // Q fragments (held in registers for the whole kernel; pre-scaled & tf32)
    uint32_t qa[8][4];
    {
        const float* Qb = g_qkv + (size_t)(b * S_ + q0 + wid * 16) * H3_ + head * HD_;
#pragma unroll
        for (int ks = 0; ks < 8; ++ks) {
            qa[ks][0] = __float_as_uint(Qb[(size_t)lr * H3_ + ks * 8 + lk]);
            qa[ks][1] = __float_as_uint(Qb[(size_t)(lr + 8) * H3_ + ks * 8 + lk]);
            qa[ks][2] = __float_as_uint(Qb[(size_t)lr * H3_ + ks * 8 + lk + 4]);
            qa[ks][3] = __float_as_uint(Qb[(size_t)(lr + 8) * H3_ + ks * 8 + lk + 4]);
        }
    }

    float m0 = -1e30f, m1 = -1e30f, l0 = 0.f, l1 = 0.f;
    float o[8][4];
#pragma unroll
    for (int nt = 0; nt < 8; ++nt)
#pragma unroll
        for (int q = 0; q < 4; ++q) o[nt][q] = 0.f;

    float* Pw = Ps + wid * 16 * PS_;

    attn_load_kv(sb, gkv, 0, tid);

    for (int t = 0; t < 32; ++t) {
        if (t < 31) {
            attn_load_kv(sb, gkv, t + 1, tid);
            asm volatile("cp.async.wait_group 1;" ::: "memory");
        } else {
            asm volatile("cp.async.wait_group 0;" ::: "memory");
        }
        __syncthreads();

        const float* Kt = Ks + (t & 1) * 64 * KVS;
        const float* Vt = Vs + (t & 1) * 64 * KVS;

        // ---- scores = Q @ K^T (pre-scaled) ----
        float sc[8][4];
#pragma unroll
        for (int nt = 0; nt < 8; ++nt) {
#pragma unroll
            for (int q = 0; q < 4; ++q) sc[nt][q] = 0.f;
#pragma unroll
            for (int ks = 0; ks < 8; ++ks) {
                uint32_t b0 = __float_as_uint(Kt[(nt * 8 + lr) * KVS + ks * 8 + lk]);
                uint32_t b1 = __float_as_uint(Kt[(nt * 8 + lr) * KVS + ks * 8 + lk + 4]);
                mma1688(sc[nt], qa[ks], b0, b1);
            }
        }

        // ---- online softmax (rows lr and lr+8; quad = lanes sharing lr) ----
        float tm0 = -1e30f, tm1 = -1e30f;
#pragma unroll
        for (int nt = 0; nt < 8; ++nt) {
            tm0 = fmaxf(tm0, fmaxf(sc[nt][0], sc[nt][1]));
            tm1 = fmaxf(tm1, fmaxf(sc[nt][2], sc[nt][3]));
        }
        tm0 = fmaxf(tm0, __shfl_xor_sync(0xffffffffu, tm0, 1));
        tm0 = fmaxf(tm0, __shfl_xor_sync(0xffffffffu, tm0, 2));
        tm1 = fmaxf(tm1, __shfl_xor_sync(0xffffffffu, tm1, 1));
        tm1 = fmaxf(tm1, __shfl_xor_sync(0xffffffffu, tm1, 2));
        float nm0 = fmaxf(m0, tm0), nm1 = fmaxf(m1, tm1);
        float a0 = __expf(m0 - nm0), a1 = __expf(m1 - nm1);
        m0 = nm0; m1 = nm1;

        float rs0 = 0.f, rs1 = 0.f;
#pragma unroll
        for (int nt = 0; nt < 8; ++nt) {
            float p0 = __expf(sc[nt][0] - nm0);
            float p1 = __expf(sc[nt][1] - nm0);
            float p2 = __expf(sc[nt][2] - nm1);
            float p3 = __expf(sc[nt][3] - nm1);
            rs0 += p0 + p1;
            rs1 += p2 + p3;
            *(float2*)(Pw + lr * PS_ + nt * 8 + lk * 2) =
                make_float2(to_tf32(p0), to_tf32(p1));
            *(float2*)(Pw + (lr + 8) * PS_ + nt * 8 + lk * 2) =
                make_float2(to_tf32(p2), to_tf32(p3));
        }
        rs0 += __shfl_xor_sync(0xffffffffu, rs0, 1);
        rs0 += __shfl_xor_sync(0xffffffffu, rs0, 2);
        rs1 += __shfl_xor_sync(0xffffffffu, rs1, 1);
        rs1 += __shfl_xor_sync(0xffffffffu, rs1, 2);
        l0 = l0 * a0 + rs0;
        l1 = l1 * a1 + rs1;
#pragma unroll
        for (int nt = 0; nt < 8; ++nt) {
            o[nt][0] *= a0; o[nt][1] *= a0;
            o[nt][2] *= a1; o[nt][3] *= a1;
        }
        __syncwarp();

        // ---- O += P @ V  (B-frag read of V as V^T via indexing) ----
#pragma unroll
        for (int ks = 0; ks < 8; ++ks) {
            uint32_t pa[4];
            pa[0] = __float_as_uint(Pw[lr * PS_ + ks * 8 + lk]);
            pa[1] = __float_as_uint(Pw[(lr + 8) * PS_ + ks * 8 + lk]);
            pa[2] = __float_as_uint(Pw[lr * PS_ + ks * 8 + lk + 4]);
            pa[3] = __float_as_uint(Pw[(lr + 8) * PS_ + ks * 8 + lk + 4]);
#pragma unroll
            for (int nt = 0; nt < 8; ++nt) {
                uint32_t b0 = __float_as_uint(Vt[(ks * 8 + lk) * KVS + nt * 8 + lr]);
                uint32_t b1 = __float_as_uint(Vt[(ks * 8 + lk + 4) * KVS + nt * 8 + lr]);
                mma1688(o[nt], pa, b0, b1);
            }
        }
        __syncthreads();
    }

    float inv0 = 1.f / l0, inv1 = 1.f / l1;
    int r = b * S_ + q0 + wid * 16 + lr;
    float* ob = g_o + (size_t)r * H_ + head * HD_;
#pragma unroll
    for (int nt = 0; nt < 8; ++nt) {
        *(float2*)(ob + nt * 8 + lk * 2) =
            make_float2(to_tf32(o[nt][0] * inv0), to_tf32(o[nt][1] * inv0));
        *(float2*)(ob + (size_t)8 * H_ + nt * 8 + lk * 2) =
            make_float2(to_tf32(o[nt][2] * inv1), to_tf32(o[nt][3] * inv1));
    }
}

// ============================================================
extern "C" void kernel_launch(void* const* d_in, const int* in_sizes, int n_in,
                              void* d_out, int out_size) {
    (void)in_sizes; (void)n_in; (void)out_size;
    const float* x     = (const float*)d_in[0];
    const float* ada   = (const float*)d_in[1];
    const float* freqs = (const float*)d_in[2];
    const float* w_qkv = (const float*)d_in[3];
    const float* w_o   = (const float*)d_in[4];
    const float* ln_w  = (const float*)d_in[5];
    const float* mod_w = (const float*)d_in[6];
    const float* mod_b = (const float*)d_in[7];
    const float* qn_w  = (const float*)d_in[8];
    const float* kn_w  = (const float*)d_in[9];
    float* out = (float*)d_out;

    const int SMEM_DYN = 4 * STG_BYTES;   // 81920 bytes
    cudaFuncSetAttribute(tc_gemm, cudaFuncAttributeMaxDynamicSharedMemorySize, SMEM_DYN);
    cudaFuncSetAttribute(attn_mma_kernel, cudaFuncAttributeMaxDynamicSharedMemorySize, ATT_SMEM);

    mod_kernel<<<768, 256>>>(ada, mod_w, mod_b);
    round_w_kernel<<<4096, 256>>>(w_qkv, w_o);
    ln_mod_kernel<<<R_, 256>>>(x, ln_w);
    tc_gemm<<<dim3(H3_ / 128, R_ / 128), 256, SMEM_DYN>>>(nullptr, H3_, 0);
    qknorm_rope_kernel<<<R_, 256>>>(freqs, qn_w, kn_w);
    attn_mma_kernel<<<dim3(S_ / 128, B_ * NH_), 256, ATT_SMEM>>>();
    tc_gemm<<<dim3(H_ / 128, R_ / 128), 256, SMEM_DYN>>>(out, H_, 1);
}

// round 11
// speedup vs baseline: 2.9695x; 1.0565x over previous
#include <cuda_runtime.h>
#include <cstdint>
#include <math.h>

#define B_ 2
#define S_ 2048
#define H_ 1024
#define NH_ 16
#define HD_ 64
#define H3_ 3072
#define R_ 4096   // B*S

// ---- scratch (static device globals; no runtime allocation) ----
__device__ __align__(256) float g_mod[B_ * H3_];           // [B, 3H] (scale|shift|gate)
__device__ __align__(256) float g_h[(size_t)R_ * H_];      // modulated LN output (tf32-rounded)
__device__ __align__(256) float g_qkv[(size_t)R_ * H3_];   // qkv projections (tf32-rounded)
__device__ __align__(256) float g_o[(size_t)R_ * H_];      // attention output (tf32-rounded)
__device__ __align__(256) float g_w1[(size_t)H3_ * H_];    // tf32-rounded w_qkv
__device__ __align__(256) float g_w2[(size_t)H_ * H_];     // tf32-rounded w_o

// ============================================================
// helpers
// ============================================================
__device__ __forceinline__ float warp_sum(float v) {
#pragma unroll
    for (int o = 16; o; o >>= 1) v += __shfl_xor_sync(0xffffffffu, v, o);
    return v;
}

__device__ __forceinline__ float to_tf32(float x) {
    float r;
    asm("cvt.rna.tf32.f32 %0, %1;" : "=f"(r) : "f"(x));
    return r;
}

__device__ __forceinline__ uint32_t cvta_smem(const void* p) {
    uint32_t a;
    asm("{ .reg .u64 t; cvta.to.shared.u64 t, %1; cvt.u32.u64 %0, t; }" : "=r"(a) : "l"(p));
    return a;
}

__device__ __forceinline__ void cp_async16(uint32_t dst, const void* src) {
    asm volatile("cp.async.cg.shared.global [%0], [%1], 16;" :: "r"(dst), "l"(src));
}

// mma.sync tf32: D[16x8] += A[16x8] * B[8x8]   (portable, sm_80+)
__device__ __forceinline__ void mma1688(float* d, const uint32_t* a, uint32_t b0, uint32_t b1) {
    asm volatile(
        "mma.sync.aligned.m16n8k8.row.col.f32.tf32.tf32.f32 "
        "{%0,%1,%2,%3}, {%4,%5,%6,%7}, {%8,%9}, {%0,%1,%2,%3};"
        : "+f"(d[0]), "+f"(d[1]), "+f"(d[2]), "+f"(d[3])
        : "r"(a[0]), "r"(a[1]), "r"(a[2]), "r"(a[3]), "r"(b0), "r"(b1));
}

// ldmatrix x4: four m8n8 b16 matrices (lane i supplies row addr for matrix i/8)
__device__ __forceinline__ void ldsm4(uint32_t* r, uint32_t addr) {
    asm volatile("ldmatrix.sync.aligned.m8n8.x4.shared.b16 {%0,%1,%2,%3}, [%4];"
                 : "=r"(r[0]), "=r"(r[1]), "=r"(r[2]), "=r"(r[3]) : "r"(addr));
}

// ============================================================
// 0) round weights fp32 -> tf32 (RNA)
// ============================================================
__global__ void __launch_bounds__(256) round_w_kernel(const float* __restrict__ wq,
                                                      const float* __restrict__ wo) {
    const size_t n1 = (size_t)H3_ * H_ / 4;
    const size_t n2 = (size_t)H_ * H_ / 4;
    size_t i = (size_t)blockIdx.x * 256 + threadIdx.x;
    if (i < n1) {
        float4 v = ((const float4*)wq)[i];
        v.x = to_tf32(v.x); v.y = to_tf32(v.y); v.z = to_tf32(v.z); v.w = to_tf32(v.w);
        ((float4*)g_w1)[i] = v;
    } else if (i < n1 + n2) {
        size_t j = i - n1;
        float4 v = ((const float4*)wo)[j];
        v.x = to_tf32(v.x); v.y = to_tf32(v.y); v.z = to_tf32(v.z); v.w = to_tf32(v.w);
        ((float4*)g_w2)[j] = v;
    }
}

// ============================================================
// 1) mod = silu(ada) @ mod_w^T + mod_b       (one warp per output)
// ============================================================
__global__ void __launch_bounds__(256) mod_kernel(const float* __restrict__ ada,
                                                  const float* __restrict__ mw,
                                                  const float* __restrict__ mb) {
    int gw = (blockIdx.x * 256 + threadIdx.x) >> 5;
    int lane = threadIdx.x & 31;
    int b = gw / H3_, j = gw % H3_;
    const float* ar = ada + b * 1024;
    const float* wr = mw + (size_t)j * 1024;
    float acc = 0.f;
#pragma unroll 4
    for (int a = lane; a < 1024; a += 32) {
        float v = ar[a];
        float s = v / (1.f + __expf(-v));
        acc = fmaf(s, wr[a], acc);
    }
    acc = warp_sum(acc);
    if (lane == 0) g_mod[gw] = acc + mb[j];
}

// ============================================================
// 2) h = LN(x)*ln_w*(scale+1) + shift   (tf32-rounded for GEMM A)
// ============================================================
__global__ void __launch_bounds__(256) ln_mod_kernel(const float* __restrict__ x,
                                                     const float* __restrict__ ln_w) {
    int row = blockIdx.x;
    int tid = threadIdx.x;
    int b = row >> 11;

    float4 xv = ((const float4*)x)[(size_t)row * 256 + tid];
    float sum = xv.x + xv.y + xv.z + xv.w;
    float sq  = xv.x * xv.x + xv.y * xv.y + xv.z * xv.z + xv.w * xv.w;
    sum = warp_sum(sum);
    sq  = warp_sum(sq);

    __shared__ float rs[8], rq[8], mv[2];
    int warp = tid >> 5, lane = tid & 31;
    if (lane == 0) { rs[warp] = sum; rq[warp] = sq; }
    __syncthreads();
    if (tid == 0) {
        float s = 0.f, q = 0.f;
#pragma unroll
        for (int w = 0; w < 8; ++w) { s += rs[w]; q += rq[w]; }
        float mean = s * (1.f / 1024.f);
        float var  = q * (1.f / 1024.f) - mean * mean;
        mv[0] = mean;
        mv[1] = rsqrtf(var + 1e-5f);
    }
    __syncthreads();
    float mean = mv[0], rstd = mv[1];

    float4 lw = ((const float4*)ln_w)[tid];
    const float* mp = g_mod + b * H3_;
    float4 sc = ((const float4*)mp)[tid];
    float4 sh = ((const float4*)(mp + H_))[tid];

    float4 h;
    h.x = to_tf32((xv.x - mean) * rstd * lw.x * (sc.x + 1.f) + sh.x);
    h.y = to_tf32((xv.y - mean) * rstd * lw.y * (sc.y + 1.f) + sh.y);
    h.z = to_tf32((xv.z - mean) * rstd * lw.z * (sc.z + 1.f) + sh.z);
    h.w = to_tf32((xv.w - mean) * rstd * lw.w * (sc.w + 1.f) + sh.w);
    ((float4*)g_h)[(size_t)row * 256 + tid] = h;
}

// ============================================================
// 3/6) tf32 mma.sync GEMM NT: C[M,N] = A[M,1024] * B[N,1024]^T
//      128x128 CTA tile, BK=16, 4-stage cp.async, 8 warps (32x64 each).
//      Fragments loaded via ldmatrix (stride 20 floats = conflict-free LDSM).
//      B tile base = stage base + 10240 BYTES (2560 floats).
// ============================================================
#define GK_ 1024
#define GNIT 64                 // GK_/16
#define STG_FLOATS 5120         // per stage: A(2560) + B(2560)
#define STG_BYTES  20480

__device__ __forceinline__ void gemm_load_stage(uint32_t sb, const float* A, const float* Bm,
                                                int row0, int col0, int it, int tid) {
    int s = it & 3;
    int krow = it * 16;
    int r = tid >> 1;                 // 0..127
    int off = (tid & 1) * 8;          // 0 or 8 floats
    uint32_t base = sb + s * STG_BYTES;
    const float* ga = A + (size_t)(row0 + r) * GK_ + krow + off;
    uint32_t da = base + (r * 20 + off) * 4;
    cp_async16(da, ga);
    cp_async16(da + 16, ga + 4);
    const float* gb = Bm + (size_t)(col0 + r) * GK_ + krow + off;
    uint32_t db = base + 10240 + (r * 20 + off) * 4;   // B tile: +10240 bytes
    cp_async16(db, gb);
    cp_async16(db + 16, gb + 4);
    asm volatile("cp.async.commit_group;" ::: "memory");
}

__global__ void __launch_bounds__(256, 2) tc_gemm(float* __restrict__ Cext, int N, int mode) {
    extern __shared__ float sm[];
    const float* A  = mode ? g_o : g_h;
    const float* Bm = mode ? g_w2 : g_w1;
    float* C = mode ? Cext : g_qkv;

    uint32_t sb = cvta_smem(sm);
    int tid = threadIdx.x;
    int wid = tid >> 5, lane = tid & 31;
    int warp_m = wid & 3, warp_n = wid >> 2;
    int row0 = blockIdx.y << 7, col0 = blockIdx.x << 7;

    int sub = lane & 7, mi = lane >> 3;
    // A-frag: m0..m3 = (rows+0,k+0),(rows+8,k+0),(rows+0,k+4),(rows+8,k+4)
    uint32_t a_off = ((uint32_t)(((mi & 1) * 8 + sub) * 20 + (mi >> 1) * 4)) * 4;
    // B-frag pair (nt, nt+1): m0..m3 = (nt,k0),(nt,k4),(nt+1,k0),(nt+1,k4)
    uint32_t b_off = 10240u + ((uint32_t)(((mi >> 1) * 8 + sub) * 20 + (mi & 1) * 4)) * 4;

    float acc[2][8][4];
#pragma unroll
    for (int i = 0; i < 2; ++i)
#pragma unroll
        for (int j = 0; j < 8; ++j)
#pragma unroll
            for (int q = 0; q < 4; ++q) acc[i][j][q] = 0.f;

    gemm_load_stage(sb, A, Bm, row0, col0, 0, tid);
    gemm_load_stage(sb, A, Bm, row0, col0, 1, tid);
    gemm_load_stage(sb, A, Bm, row0, col0, 2, tid);

    for (int it = 0; it < GNIT; ++it) {
        asm volatile("cp.async.wait_group 2;" ::: "memory");
        __syncthreads();

        uint32_t st = sb + (it & 3) * STG_BYTES;
#pragma unroll
        for (int k8 = 0; k8 < 16; k8 += 8) {
            uint32_t a0[4], a1[4];
            ldsm4(a0, st + a_off + (uint32_t)((warp_m * 32) * 20 + k8) * 4);
            ldsm4(a1, st + a_off + (uint32_t)((warp_m * 32 + 16) * 20 + k8) * 4);
#pragma unroll
            for (int ntp = 0; ntp < 4; ++ntp) {
                uint32_t bb[4];
                ldsm4(bb, st + b_off + (uint32_t)((warp_n * 64 + ntp * 16) * 20 + k8) * 4);
                mma1688(acc[0][2 * ntp],     a0, bb[0], bb[1]);
                mma1688(acc[1][2 * ntp],     a1, bb[0], bb[1]);
                mma1688(acc[0][2 * ntp + 1], a0, bb[2], bb[3]);
                mma1688(acc[1][2 * ntp + 1], a1, bb[2], bb[3]);
            }
        }
        __syncthreads();
        if (it + 3 < GNIT) gemm_load_stage(sb, A, Bm, row0, col0, it + 3, tid);
    }

    int lr = lane >> 2, lk = lane & 3;
    // epilogue (mode 0: round to tf32 for attention consumers; mode 1: gate)
#pragma unroll
    for (int mt = 0; mt < 2; ++mt) {
        int r = row0 + warp_m * 32 + mt * 16 + lr;
        int gb = (r >> 11) * H3_ + 2 * H_;
#pragma unroll
        for (int nt = 0; nt < 8; ++nt) {
            int c = col0 + warp_n * 64 + nt * 8 + lk * 2;
            float2 v0 = make_float2(acc[mt][nt][0], acc[mt][nt][1]);
            float2 v1 = make_float2(acc[mt][nt][2], acc[mt][nt][3]);
            if (mode) {
                float gx = g_mod[gb + c], gy = g_mod[gb + c + 1];
                v0.x *= gx; v0.y *= gy;
                v1.x *= gx; v1.y *= gy;
            } else {
                v0.x = to_tf32(v0.x); v0.y = to_tf32(v0.y);
                v1.x = to_tf32(v1.x); v1.y = to_tf32(v1.y);
            }
            *(float2*)(C + (size_t)r * N + c) = v0;
            *(float2*)(C + (size_t)(r + 8) * N + c) = v1;
        }
    }
}

// ============================================================
// 4) per-head QK layernorm + RoPE, in place on g_qkv
//    q gets the 1/sqrt(hd)=0.125 attention scale folded in; outputs tf32-rounded
// ============================================================
__global__ void __launch_bounds__(256) qknorm_rope_kernel(const float* __restrict__ freqs,
                                                          const float* __restrict__ qn_w,
                                                          const float* __restrict__ kn_w) {
    int row = blockIdx.x;
    int s = row & (S_ - 1);
    int warp = threadIdx.x >> 5;
    int lane = threadIdx.x & 31;

    float f0 = freqs[(s * 32 + lane) * 2 + 0];
    float f1 = freqs[(s * 32 + lane) * 2 + 1];

    for (int task = warp; task < 32; task += 8) {
        int type = task >> 4;
        int head = task & 15;
        size_t base = (size_t)row * H3_ + type * H_ + head * HD_;
        float v0 = g_qkv[base + lane * 2];
        float v1 = g_qkv[base + lane * 2 + 1];
        float sum = warp_sum(v0 + v1);
        float sq  = warp_sum(v0 * v0 + v1 * v1);
        float mean = sum * (1.f / 64.f);
        float var  = sq * (1.f / 64.f) - mean * mean;
        float rstd = rsqrtf(var + 1e-5f);
        const float* w = type ? kn_w : qn_w;
        float n0 = (v0 - mean) * rstd * w[lane * 2];
        float n1 = (v1 - mean) * rstd * w[lane * 2 + 1];
        float r0 = n0 * f0 - n1 * f1;
        float r1 = n1 * f0 + n0 * f1;
        float qs = type ? 1.f : 0.125f;
        g_qkv[base + lane * 2]     = to_tf32(r0 * qs);
        g_qkv[base + lane * 2 + 1] = to_tf32(r1 * qs);
    }
}

// ============================================================
// 5) flash attention (non-causal), tf32 mma.sync + ldmatrix
//    grid = (S/128, B*NH), 256 threads (8 warps x m16 q-rows)
//    K double-buffered stride 68 (LDSM); V double-buffered stride 72,
//    transposed per-tile into VT stride 68 (LDSM); P per-warp stride 68 (LDSM)
// ============================================================
#define KS_ 68
#define VS_ 72
#define VT_S 68
#define PS_ 68
#define OFF_VB (2 * 64 * KS_)            // 8704
#define OFF_VT (OFF_VB + 2 * 64 * VS_)   // 17920
#define OFF_P  (OFF_VT + 64 * VT_S)      // 22272
#define ATT_SMEM ((OFF_P + 8 * 16 * PS_) * 4)   // 123904 bytes

__device__ __forceinline__ void attn_load_kv(uint32_t sb, const float* gkv, int t, int tid) {
    int s = t & 1;
    int r = tid >> 2;                 // 0..63 (key within tile)
    int cc = (tid & 3) * 16;          // dim chunk
    const float* kg = gkv + (size_t)(t * 64 + r) * H3_ + cc;
    const float* vg = kg + H_;
    uint32_t kd = sb + (uint32_t)(s * 64 * KS_ + r * KS_ + cc) * 4;
    uint32_t vd = sb + (uint32_t)(OFF_VB + s * 64 * VS_ + r * VS_ + cc) * 4;
#pragma unroll
    for (int i = 0; i < 4; ++i) {
        cp_async16(kd + i * 16, kg + i * 4);
        cp_async16(vd + i * 16, vg + i * 4);
    }
    asm volatile("cp.async.commit_group;" ::: "memory");
}

__global__ void __launch_bounds__(256, 1) attn_mma_kernel() {
    extern __shared__ float sm[];
    uint32_t sb = cvta_smem(sm);

    int tid = threadIdx.x, wid = tid >> 5, lane = tid & 31;
    int lr = lane >> 2, lk = lane & 3;
    int sub = lane & 7, mi = lane >> 3;
    int q0 = blockIdx.x << 7;
    int b = blockIdx.y >> 4, head = blockIdx.y & 15;

    const float* gkv = g_qkv + (size_t)b * S_ * H3_ + H_ + head * HD_;  // K base (V = +H_)

    // per-lane LDSM offsets (bytes)
    // K B-frag: m0..m3 = dims (+0..3),(+4..7),(+8..11),(+12..15), keys = block+sub
    uint32_t k_loff = (uint32_t)(sub * KS_ + (mi >> 1) * 8 + (mi & 1) * 4) * 4;
    // VT B-frag: m0..m3 = (dims+0..7,keys+0..3),(d+0..7,k+4..7),(d+8..15,k+0..3),(d+8..15,k+4..7)
    uint32_t vt_loff = (uint32_t)(((mi >> 1) * 8 + sub) * VT_S + (mi & 1) * 4) * 4;
    // P A-frag: m0..m3 = (rows+0,k0),(rows+8,k0),(rows+0,k4),(rows+8,k4)
    uint32_t p_loff = (uint32_t)(((mi & 1) * 8 + sub) * PS_ + (mi >> 1) * 4) * 4;

    // Q fragments (registers for the whole kernel; pre-scaled & tf32)
    uint32_t qa[8][4];
    {
        const float* Qb = g_qkv + (size_t)(b * S_ + q0 + wid * 16) * H3_ + head * HD_;
#pragma unroll
        for (int ks = 0; ks < 8; ++ks) {
            qa[ks][0] = __float_as_uint(Qb[(size_t)lr * H3_ + ks * 8 + lk]);
            qa[ks][1] = __float_as_uint(Qb[(size_t)(lr + 8) * H3_ + ks * 8 + lk]);
            qa[ks][2] = __float_as_uint(Qb[(size_t)lr * H3_ + ks * 8 + lk + 4]);
            qa[ks][3] = __float_as_uint(Qb[(size_t)(lr + 8) * H3_ + ks * 8 + lk + 4]);
        }
    }

    float m0 = -1e30f, m1 = -1e30f, l0 = 0.f, l1 = 0.f;
    float o[8][4];
#pragma unroll
    for (int nt = 0; nt < 8; ++nt)
#pragma unroll
        for (int q = 0; q < 4; ++q) o[nt][q] = 0.f;

    float* Pw = sm + OFF_P + wid * 16 * PS_;
    uint32_t Pwb = sb + (uint32_t)(OFF_P + wid * 16 * PS_) * 4;
    uint32_t VTb = sb + (uint32_t)OFF_VT * 4;

    attn_load_kv(sb, gkv, 0, tid);

    for (int t = 0; t < 32; ++t) {
        if (t < 31) {
            attn_load_kv(sb, gkv, t + 1, tid);
            asm volatile("cp.async.wait_group 1;" ::: "memory");
        } else {
            asm volatile("cp.async.wait_group 0;" ::: "memory");
        }
        __syncthreads();   // tile t arrived; prior iter's VT/K reads complete

        // ---- transpose V tile: Vbuf[key][dim] -> VT[dim][key] ----
        {
            int key = tid & 63, dbase = (tid >> 6) * 16;
            const float* src = sm + OFF_VB + (t & 1) * 64 * VS_ + key * VS_ + dbase;
            float4 va = ((const float4*)src)[0];
            float4 vb4 = ((const float4*)src)[1];
            float4 vc = ((const float4*)src)[2];
            float4 vd = ((const float4*)src)[3];
            float vv[16] = {va.x, va.y, va.z, va.w, vb4.x, vb4.y, vb4.z, vb4.w,
                            vc.x, vc.y, vc.z, vc.w, vd.x, vd.y, vd.z, vd.w};
            float* vt = sm + OFF_VT;
#pragma unroll
            for (int d = 0; d < 16; ++d) vt[(dbase + d) * VT_S + key] = vv[d];
        }

        uint32_t Kst = sb + (uint32_t)((t & 1) * 64 * KS_) * 4;

        // ---- scores = Q @ K^T (pre-scaled) ----
        float sc[8][4];
#pragma unroll
        for (int nt = 0; nt < 8; ++nt) {
            uint32_t kb[16];
#pragma unroll
            for (int p = 0; p < 4; ++p)
                ldsm4(kb + 4 * p, Kst + k_loff + (uint32_t)(nt * 8 * KS_ + p * 16) * 4);
#pragma unroll
            for (int q = 0; q < 4; ++q) sc[nt][q] = 0.f;
#pragma unroll
            for (int ks = 0; ks < 8; ++ks)
                mma1688(sc[nt], qa[ks], kb[2 * ks], kb[2 * ks + 1]);
        }

        // ---- online softmax (rows lr and lr+8; quad lanes share a row) ----
        float tm0 = -1e30f, tm1 = -1e30f;
#pragma unroll
        for (int nt = 0; nt < 8; ++nt) {
            tm0 = fmaxf(tm0, fmaxf(sc[nt][0], sc[nt][1]));
            tm1 = fmaxf(tm1, fmaxf(sc[nt][2], sc[nt][3]));
        }
        tm0 = fmaxf(tm0, __shfl_xor_sync(0xffffffffu, tm0, 1));
        tm0 = fmaxf(tm0, __shfl_xor_sync(0xffffffffu, tm0, 2));
        tm1 = fmaxf(tm1, __shfl_xor_sync(0xffffffffu, tm1, 1));
        tm1 = fmaxf(tm1, __shfl_xor_sync(0xffffffffu, tm1, 2));
        float nm0 = fmaxf(m0, tm0), nm1 = fmaxf(m1, tm1);
        float a0 = __expf(m0 - nm0), a1 = __expf(m1 - nm1);
        m0 = nm0; m1 = nm1;

        float rs0 = 0.f, rs1 = 0.f;
#pragma unroll
        for (int nt = 0; nt < 8; ++nt) {
            float p0 = __expf(sc[nt][0] - nm0);
            float p1 = __expf(sc[nt][1] - nm0);
            float p2 = __expf(sc[nt][2] - nm1);
            float p3 = __expf(sc[nt][3] - nm1);
            rs0 += p0 + p1;
            rs1 += p2 + p3;
            *(float2*)(Pw + lr * PS_ + nt * 8 + lk * 2) =
                make_float2(to_tf32(p0), to_tf32(p1));
            *(float2*)(Pw + (lr + 8) * PS_ + nt * 8 + lk * 2) =
                make_float2(to_tf32(p2), to_tf32(p3));
        }
        rs0 += __shfl_xor_sync(0xffffffffu, rs0, 1);
        rs0 += __shfl_xor_sync(0xffffffffu, rs0, 2);
        rs1 += __shfl_xor_sync(0xffffffffu, rs1, 1);
        rs1 += __shfl_xor_sync(0xffffffffu, rs1, 2);
        l0 = l0 * a0 + rs0;
        l1 = l1 * a1 + rs1;
#pragma unroll
        for (int nt = 0; nt < 8; ++nt) {
            o[nt][0] *= a0; o[nt][1] *= a0;
            o[nt][2] *= a1; o[nt][3] *= a1;
        }
        __syncthreads();   // VT transposed + P visible

        // ---- O += P @ V  (P A-frags + VT B-frags via LDSM) ----
#pragma unroll
        for (int ks = 0; ks < 8; ++ks) {
            uint32_t pa[4];
            ldsm4(pa, Pwb + p_loff + (uint32_t)(ks * 8) * 4);
#pragma unroll
            for (int ntp = 0; ntp < 4; ++ntp) {
                uint32_t vb[4];
                ldsm4(vb, VTb + vt_loff + (uint32_t)(ntp * 16 * VT_S + ks * 8) * 4);
                mma1688(o[2 * ntp],     pa, vb[0], vb[1]);
                mma1688(o[2 * ntp + 1], pa, vb[2], vb[3]);
            }
        }
    }

    float inv0 = 1.f / l0, inv1 = 1.f / l1;
    int r = b * S_ + q0 + wid * 16 + lr;
    float* ob = g_o + (size_t)r * H_ + head * HD_;
#pragma unroll
    for (int nt = 0; nt < 8; ++nt) {
        *(float2*)(ob + nt * 8 + lk * 2) =
            make_float2(to_tf32(o[nt][0] * inv0), to_tf32(o[nt][1] * inv0));
        *(float2*)(ob + (size_t)8 * H_ + nt * 8 + lk * 2) =
            make_float2(to_tf32(o[nt][2] * inv1), to_tf32(o[nt][3] * inv1));
    }
}

// ============================================================
extern "C" void kernel_launch(void* const* d_in, const int* in_sizes, int n_in,
                              void* d_out, int out_size) {
    (void)in_sizes; (void)n_in; (void)out_size;
    const float* x     = (const float*)d_in[0];
    const float* ada   = (const float*)d_in[1];
    const float* freqs = (const float*)d_in[2];
    const float* w_qkv = (const float*)d_in[3];
    const float* w_o   = (const float*)d_in[4];
    const float* ln_w  = (const float*)d_in[5];
    const float* mod_w = (const float*)d_in[6];
    const float* mod_b = (const float*)d_in[7];
    const float* qn_w  = (const float*)d_in[8];
    const float* kn_w  = (const float*)d_in[9];
    float* out = (float*)d_out;

    const int SMEM_DYN = 4 * STG_BYTES;   // 81920 bytes
    cudaFuncSetAttribute(tc_gemm, cudaFuncAttributeMaxDynamicSharedMemorySize, SMEM_DYN);
    cudaFuncSetAttribute(attn_mma_kernel, cudaFuncAttributeMaxDynamicSharedMemorySize, ATT_SMEM);

    mod_kernel<<<768, 256>>>(ada, mod_w, mod_b);
    round_w_kernel<<<4096, 256>>>(w_qkv, w_o);
    ln_mod_kernel<<<R_, 256>>>(x, ln_w);
    tc_gemm<<<dim3(H3_ / 128, R_ / 128), 256, SMEM_DYN>>>(nullptr, H3_, 0);
    qknorm_rope_kernel<<<R_, 256>>>(freqs, qn_w, kn_w);
    attn_mma_kernel<<<dim3(S_ / 128, B_ * NH_), 256, ATT_SMEM>>>();
    tc_gemm<<<dim3(H_ / 128, R_ / 128), 256, SMEM_DYN>>>(out, H_, 1);
}

// round 12
// speedup vs baseline: 3.0576x; 1.0297x over previous
#include <cuda_runtime.h>
#include <cstdint>
#include <math.h>

#define B_ 2
#define S_ 2048
#define H_ 1024
#define NH_ 16
#define HD_ 64
#define H3_ 3072
#define R_ 4096   // B*S

// ---- scratch (static device globals; no runtime allocation) ----
__device__ __align__(256) float g_mod[B_ * H3_];           // [B, 3H] (scale|shift|gate)
__device__ __align__(256) float g_h[(size_t)R_ * H_];      // modulated LN output (tf32-rounded)
__device__ __align__(256) float g_qkv[(size_t)R_ * H3_];   // qkv projections (tf32-rounded)
__device__ __align__(256) float g_o[(size_t)R_ * H_];      // attention output (tf32-rounded)
__device__ __align__(256) float g_w1[(size_t)H3_ * H_];    // tf32-rounded w_qkv
__device__ __align__(256) float g_w2[(size_t)H_ * H_];     // tf32-rounded w_o

// ============================================================
// helpers
// ============================================================
__device__ __forceinline__ float warp_sum(float v) {
#pragma unroll
    for (int o = 16; o; o >>= 1) v += __shfl_xor_sync(0xffffffffu, v, o);
    return v;
}

__device__ __forceinline__ float to_tf32(float x) {
    float r;
    asm("cvt.rna.tf32.f32 %0, %1;" : "=f"(r) : "f"(x));
    return r;
}

__device__ __forceinline__ uint32_t cvta_smem(const void* p) {
    uint32_t a;
    asm("{ .reg .u64 t; cvta.to.shared.u64 t, %1; cvt.u32.u64 %0, t; }" : "=r"(a) : "l"(p));
    return a;
}

__device__ __forceinline__ void cp_async16(uint32_t dst, const void* src) {
    asm volatile("cp.async.cg.shared.global [%0], [%1], 16;" :: "r"(dst), "l"(src));
}

// mma.sync tf32: D[16x8] += A[16x8] * B[8x8]   (portable, sm_80+)
__device__ __forceinline__ void mma1688(float* d, const uint32_t* a, uint32_t b0, uint32_t b1) {
    asm volatile(
        "mma.sync.aligned.m16n8k8.row.col.f32.tf32.tf32.f32 "
        "{%0,%1,%2,%3}, {%4,%5,%6,%7}, {%8,%9}, {%0,%1,%2,%3};"
        : "+f"(d[0]), "+f"(d[1]), "+f"(d[2]), "+f"(d[3])
        : "r"(a[0]), "r"(a[1]), "r"(a[2]), "r"(a[3]), "r"(b0), "r"(b1));
}

// ldmatrix x4: four m8n8 b16 matrices (lane i supplies row addr for matrix i/8)
__device__ __forceinline__ void ldsm4(uint32_t* r, uint32_t addr) {
    asm volatile("ldmatrix.sync.aligned.m8n8.x4.shared.b16 {%0,%1,%2,%3}, [%4];"
                 : "=r"(r[0]), "=r"(r[1]), "=r"(r[2]), "=r"(r[3]) : "r"(addr));
}

// ============================================================
// 0) round weights fp32 -> tf32 (RNA)
// ============================================================
__global__ void __launch_bounds__(256) round_w_kernel(const float* __restrict__ wq,
                                                      const float* __restrict__ wo) {
    const size_t n1 = (size_t)H3_ * H_ / 4;
    const size_t n2 = (size_t)H_ * H_ / 4;
    size_t i = (size_t)blockIdx.x * 256 + threadIdx.x;
    if (i < n1) {
        float4 v = ((const float4*)wq)[i];
        v.x = to_tf32(v.x); v.y = to_tf32(v.y); v.z = to_tf32(v.z); v.w = to_tf32(v.w);
        ((float4*)g_w1)[i] = v;
    } else if (i < n1 + n2) {
        size_t j = i - n1;
        float4 v = ((const float4*)wo)[j];
        v.x = to_tf32(v.x); v.y = to_tf32(v.y); v.z = to_tf32(v.z); v.w = to_tf32(v.w);
        ((float4*)g_w2)[j] = v;
    }
}

// ============================================================
// 1) mod = silu(ada) @ mod_w^T + mod_b       (one warp per output)
// ============================================================
__global__ void __launch_bounds__(256) mod_kernel(const float* __restrict__ ada,
                                                  const float* __restrict__ mw,
                                                  const float* __restrict__ mb) {
    int gw = (blockIdx.x * 256 + threadIdx.x) >> 5;
    int lane = threadIdx.x & 31;
    int b = gw / H3_, j = gw % H3_;
    const float* ar = ada + b * 1024;
    const float* wr = mw + (size_t)j * 1024;
    float acc = 0.f;
#pragma unroll 4
    for (int a = lane; a < 1024; a += 32) {
        float v = ar[a];
        float s = v / (1.f + __expf(-v));
        acc = fmaf(s, wr[a], acc);
    }
    acc = warp_sum(acc);
    if (lane == 0) g_mod[gw] = acc + mb[j];
}

// ============================================================
// 2) h = LN(x)*ln_w*(scale+1) + shift   (tf32-rounded for GEMM A)
// ============================================================
__global__ void __launch_bounds__(256) ln_mod_kernel(const float* __restrict__ x,
                                                     const float* __restrict__ ln_w) {
    int row = blockIdx.x;
    int tid = threadIdx.x;
    int b = row >> 11;

    float4 xv = ((const float4*)x)[(size_t)row * 256 + tid];
    float sum = xv.x + xv.y + xv.z + xv.w;
    float sq  = xv.x * xv.x + xv.y * xv.y + xv.z * xv.z + xv.w * xv.w;
    sum = warp_sum(sum);
    sq  = warp_sum(sq);

    __shared__ float rs[8], rq[8], mv[2];
    int warp = tid >> 5, lane = tid & 31;
    if (lane == 0) { rs[warp] = sum; rq[warp] = sq; }
    __syncthreads();
    if (tid == 0) {
        float s = 0.f, q = 0.f;
#pragma unroll
        for (int w = 0; w < 8; ++w) { s += rs[w]; q += rq[w]; }
        float mean = s * (1.f / 1024.f);
        float var  = q * (1.f / 1024.f) - mean * mean;
        mv[0] = mean;
        mv[1] = rsqrtf(var + 1e-5f);
    }
    __syncthreads();
    float mean = mv[0], rstd = mv[1];

    float4 lw = ((const float4*)ln_w)[tid];
    const float* mp = g_mod + b * H3_;
    float4 sc = ((const float4*)mp)[tid];
    float4 sh = ((const float4*)(mp + H_))[tid];

    float4 h;
    h.x = to_tf32((xv.x - mean) * rstd * lw.x * (sc.x + 1.f) + sh.x);
    h.y = to_tf32((xv.y - mean) * rstd * lw.y * (sc.y + 1.f) + sh.y);
    h.z = to_tf32((xv.z - mean) * rstd * lw.z * (sc.z + 1.f) + sh.z);
    h.w = to_tf32((xv.w - mean) * rstd * lw.w * (sc.w + 1.f) + sh.w);
    ((float4*)g_h)[(size_t)row * 256 + tid] = h;
}

// ============================================================
// 3/6) tf32 mma.sync GEMM NT: C[M,N] = A[M,1024] * B[N,1024]^T
//      128x128 CTA tile, BK=16, 4-stage cp.async, 8 warps (32x64 each).
//      Single barrier per k-iter: wait -> sync -> issue load(it+3) -> MMAs.
// ============================================================
#define GK_ 1024
#define GNIT 64                 // GK_/16
#define STG_FLOATS 5120         // per stage: A(2560) + B(2560)
#define STG_BYTES  20480

__device__ __forceinline__ void gemm_load_stage(uint32_t sb, const float* A, const float* Bm,
                                                int row0, int col0, int it, int tid) {
    int s = it & 3;
    int krow = it * 16;
    int r = tid >> 1;                 // 0..127
    int off = (tid & 1) * 8;          // 0 or 8 floats
    uint32_t base = sb + s * STG_BYTES;
    const float* ga = A + (size_t)(row0 + r) * GK_ + krow + off;
    uint32_t da = base + (r * 20 + off) * 4;
    cp_async16(da, ga);
    cp_async16(da + 16, ga + 4);
    const float* gb = Bm + (size_t)(col0 + r) * GK_ + krow + off;
    uint32_t db = base + 10240 + (r * 20 + off) * 4;   // B tile: +10240 bytes
    cp_async16(db, gb);
    cp_async16(db + 16, gb + 4);
    asm volatile("cp.async.commit_group;" ::: "memory");
}

__global__ void __launch_bounds__(256, 2) tc_gemm(float* __restrict__ Cext, int N, int mode) {
    extern __shared__ float sm[];
    const float* A  = mode ? g_o : g_h;
    const float* Bm = mode ? g_w2 : g_w1;
    float* C = mode ? Cext : g_qkv;

    uint32_t sb = cvta_smem(sm);
    int tid = threadIdx.x;
    int wid = tid >> 5, lane = tid & 31;
    int warp_m = wid & 3, warp_n = wid >> 2;
    int row0 = blockIdx.y << 7, col0 = blockIdx.x << 7;

    int sub = lane & 7, mi = lane >> 3;
    // A-frag: m0..m3 = (rows+0,k+0),(rows+8,k+0),(rows+0,k+4),(rows+8,k+4)
    uint32_t a_off = ((uint32_t)(((mi & 1) * 8 + sub) * 20 + (mi >> 1) * 4)) * 4;
    // B-frag pair (nt, nt+1): m0..m3 = (nt,k0),(nt,k4),(nt+1,k0),(nt+1,k4)
    uint32_t b_off = 10240u + ((uint32_t)(((mi >> 1) * 8 + sub) * 20 + (mi & 1) * 4)) * 4;

    float acc[2][8][4];
#pragma unroll
    for (int i = 0; i < 2; ++i)
#pragma unroll
        for (int j = 0; j < 8; ++j)
#pragma unroll
            for (int q = 0; q < 4; ++q) acc[i][j][q] = 0.f;

    gemm_load_stage(sb, A, Bm, row0, col0, 0, tid);
    gemm_load_stage(sb, A, Bm, row0, col0, 1, tid);
    gemm_load_stage(sb, A, Bm, row0, col0, 2, tid);

    for (int it = 0; it < GNIT; ++it) {
        asm volatile("cp.async.wait_group 2;" ::: "memory");   // stage it resident
        __syncthreads();   // all warps see stage it; all done reading stage (it+3)&3
        if (it + 3 < GNIT) gemm_load_stage(sb, A, Bm, row0, col0, it + 3, tid);

        uint32_t st = sb + (it & 3) * STG_BYTES;
#pragma unroll
        for (int k8 = 0; k8 < 16; k8 += 8) {
            uint32_t a0[4], a1[4];
            ldsm4(a0, st + a_off + (uint32_t)((warp_m * 32) * 20 + k8) * 4);
            ldsm4(a1, st + a_off + (uint32_t)((warp_m * 32 + 16) * 20 + k8) * 4);
#pragma unroll
            for (int ntp = 0; ntp < 4; ++ntp) {
                uint32_t bb[4];
                ldsm4(bb, st + b_off + (uint32_t)((warp_n * 64 + ntp * 16) * 20 + k8) * 4);
                mma1688(acc[0][2 * ntp],     a0, bb[0], bb[1]);
                mma1688(acc[1][2 * ntp],     a1, bb[0], bb[1]);
                mma1688(acc[0][2 * ntp + 1], a0, bb[2], bb[3]);
                mma1688(acc[1][2 * ntp + 1], a1, bb[2], bb[3]);
            }
        }
    }

    int lr = lane >> 2, lk = lane & 3;
    // epilogue (mode 0: round to tf32 for attention consumers; mode 1: gate)
#pragma unroll
    for (int mt = 0; mt < 2; ++mt) {
        int r = row0 + warp_m * 32 + mt * 16 + lr;
        int gb = (r >> 11) * H3_ + 2 * H_;
#pragma unroll
        for (int nt = 0; nt < 8; ++nt) {
            int c = col0 + warp_n * 64 + nt * 8 + lk * 2;
            float2 v0 = make_float2(acc[mt][nt][0], acc[mt][nt][1]);
            float2 v1 = make_float2(acc[mt][nt][2], acc[mt][nt][3]);
            if (mode) {
                float gx = g_mod[gb + c], gy = g_mod[gb + c + 1];
                v0.x *= gx; v0.y *= gy;
                v1.x *= gx; v1.y *= gy;
            } else {
                v0.x = to_tf32(v0.x); v0.y = to_tf32(v0.y);
                v1.x = to_tf32(v1.x); v1.y = to_tf32(v1.y);
            }
            *(float2*)(C + (size_t)r * N + c) = v0;
            *(float2*)(C + (size_t)(r + 8) * N + c) = v1;
        }
    }
}

// ============================================================
// 4) per-head QK layernorm + RoPE, in place on g_qkv
//    q gets 0.125*log2(e) folded in (softmax uses exp2); outputs tf32-rounded
// ============================================================
__global__ void __launch_bounds__(256) qknorm_rope_kernel(const float* __restrict__ freqs,
                                                          const float* __restrict__ qn_w,
                                                          const float* __restrict__ kn_w) {
    int row = blockIdx.x;
    int s = row & (S_ - 1);
    int warp = threadIdx.x >> 5;
    int lane = threadIdx.x & 31;

    float f0 = freqs[(s * 32 + lane) * 2 + 0];
    float f1 = freqs[(s * 32 + lane) * 2 + 1];

    for (int task = warp; task < 32; task += 8) {
        int type = task >> 4;
        int head = task & 15;
        size_t base = (size_t)row * H3_ + type * H_ + head * HD_;
        float v0 = g_qkv[base + lane * 2];
        float v1 = g_qkv[base + lane * 2 + 1];
        float sum = warp_sum(v0 + v1);
        float sq  = warp_sum(v0 * v0 + v1 * v1);
        float mean = sum * (1.f / 64.f);
        float var  = sq * (1.f / 64.f) - mean * mean;
        float rstd = rsqrtf(var + 1e-5f);
        const float* w = type ? kn_w : qn_w;
        float n0 = (v0 - mean) * rstd * w[lane * 2];
        float n1 = (v1 - mean) * rstd * w[lane * 2 + 1];
        float r0 = n0 * f0 - n1 * f1;
        float r1 = n1 * f0 + n0 * f1;
        float qs = type ? 1.f : (0.125f * 1.44269504088896340736f);
        g_qkv[base + lane * 2]     = to_tf32(r0 * qs);
        g_qkv[base + lane * 2 + 1] = to_tf32(r1 * qs);
    }
}

// ============================================================
// 5) flash attention (non-causal), tf32 mma.sync + ldmatrix, base-2 softmax
//    grid = (S/128, B*NH), 256 threads (8 warps x m16 q-rows)
// ============================================================
#define KS_ 68
#define VS_ 72
#define VT_S 68
#define PS_ 68
#define OFF_VB (2 * 64 * KS_)            // 8704
#define OFF_VT (OFF_VB + 2 * 64 * VS_)   // 17920
#define OFF_P  (OFF_VT + 64 * VT_S)      // 22272
#define ATT_SMEM ((OFF_P + 8 * 16 * PS_) * 4)   // 123904 bytes

__device__ __forceinline__ void attn_load_kv(uint32_t sb, const float* gkv, int t, int tid) {
    int s = t & 1;
    int r = tid >> 2;                 // 0..63 (key within tile)
    int cc = (tid & 3) * 16;          // dim chunk
    const float* kg = gkv + (size_t)(t * 64 + r) * H3_ + cc;
    const float* vg = kg + H_;
    uint32_t kd = sb + (uint32_t)(s * 64 * KS_ + r * KS_ + cc) * 4;
    uint32_t vd = sb + (uint32_t)(OFF_VB + s * 64 * VS_ + r * VS_ + cc) * 4;
#pragma unroll
    for (int i = 0; i < 4; ++i) {
        cp_async16(kd + i * 16, kg + i * 4);
        cp_async16(vd + i * 16, vg + i * 4);
    }
    asm volatile("cp.async.commit_group;" ::: "memory");
}

__global__ void __launch_bounds__(256, 1) attn_mma_kernel() {
    extern __shared__ float sm[];
    uint32_t sb = cvta_smem(sm);

    int tid = threadIdx.x, wid = tid >> 5, lane = tid & 31;
    int lr = lane >> 2, lk = lane & 3;
    int sub = lane & 7, mi = lane >> 3;
    int q0 = blockIdx.x << 7;
    int b = blockIdx.y >> 4, head = blockIdx.y & 15;

    const float* gkv = g_qkv + (size_t)b * S_ * H3_ + H_ + head * HD_;  // K base (V = +H_)

    // per-lane LDSM offsets (bytes)
    uint32_t k_loff = (uint32_t)(sub * KS_ + (mi >> 1) * 8 + (mi & 1) * 4) * 4;
    uint32_t vt_loff = (uint32_t)(((mi >> 1) * 8 + sub) * VT_S + (mi & 1) * 4) * 4;
    uint32_t p_loff = (uint32_t)(((mi & 1) * 8 + sub) * PS_ + (mi >> 1) * 4) * 4;

    // Q fragments (registers for the whole kernel; pre-scaled & tf32)
    uint32_t qa[8][4];
    {
        const float* Qb = g_qkv + (size_t)(b * S_ + q0 + wid * 16) * H3_ + head * HD_;
#pragma unroll
        for (int ks = 0; ks < 8; ++ks) {
            qa[ks][0] = __float_as_uint(Qb[(size_t)lr * H3_ + ks * 8 + lk]);
            qa[ks][1] = __float_as_uint(Qb[(size_t)(lr + 8) * H3_ + ks * 8 + lk]);
            qa[ks][2] = __float_as_uint(Qb[(size_t)lr * H3_ + ks * 8 + lk + 4]);
            qa[ks][3] = __float_as_uint(Qb[(size_t)(lr + 8) * H3_ + ks * 8 + lk + 4]);
        }
    }

    float m0 = -1e30f, m1 = -1e30f, l0 = 0.f, l1 = 0.f;
    float o[8][4];
#pragma unroll
    for (int nt = 0; nt < 8; ++nt)
#pragma unroll
        for (int q = 0; q < 4; ++q) o[nt][q] = 0.f;

    float* Pw = sm + OFF_P + wid * 16 * PS_;
    uint32_t Pwb = sb + (uint32_t)(OFF_P + wid * 16 * PS_) * 4;
    uint32_t VTb = sb + (uint32_t)OFF_VT * 4;

    attn_load_kv(sb, gkv, 0, tid);

    for (int t = 0; t < 32; ++t) {
        asm volatile("cp.async.wait_group 0;" ::: "memory");   // tile t resident
        __syncthreads();   // visible to all; prev iter's reads of buffer (t+1)&1 done
        if (t < 31) attn_load_kv(sb, gkv, t + 1, tid);

        // ---- transpose V tile: Vbuf[key][dim] -> VT[dim][key] ----
        {
            int key = tid & 63, dbase = (tid >> 6) * 16;
            const float* src = sm + OFF_VB + (t & 1) * 64 * VS_ + key * VS_ + dbase;
            float4 va = ((const float4*)src)[0];
            float4 vb4 = ((const float4*)src)[1];
            float4 vc = ((const float4*)src)[2];
            float4 vd = ((const float4*)src)[3];
            float vv[16] = {va.x, va.y, va.z, va.w, vb4.x, vb4.y, vb4.z, vb4.w,
                            vc.x, vc.y, vc.z, vc.w, vd.x, vd.y, vd.z, vd.w};
            float* vt = sm + OFF_VT;
#pragma unroll
            for (int d = 0; d < 16; ++d) vt[(dbase + d) * VT_S + key] = vv[d];
        }

        uint32_t Kst = sb + (uint32_t)((t & 1) * 64 * KS_) * 4;

        // ---- scores = Q @ K^T (pre-scaled, base-2 domain) ----
        float sc[8][4];
#pragma unroll
        for (int nt = 0; nt < 8; ++nt) {
            uint32_t kb[16];
#pragma unroll
            for (int p = 0; p < 4; ++p)
                ldsm4(kb + 4 * p, Kst + k_loff + (uint32_t)(nt * 8 * KS_ + p * 16) * 4);
#pragma unroll
            for (int q = 0; q < 4; ++q) sc[nt][q] = 0.f;
#pragma unroll
            for (int ks = 0; ks < 8; ++ks)
                mma1688(sc[nt], qa[ks], kb[2 * ks], kb[2 * ks + 1]);
        }

        // ---- online softmax, base 2 (rows lr, lr+8; quad lanes share a row) ----
        float tm0 = -1e30f, tm1 = -1e30f;
#pragma unroll
        for (int nt = 0; nt < 8; ++nt) {
            tm0 = fmaxf(tm0, fmaxf(sc[nt][0], sc[nt][1]));
            tm1 = fmaxf(tm1, fmaxf(sc[nt][2], sc[nt][3]));
        }
        tm0 = fmaxf(tm0, __shfl_xor_sync(0xffffffffu, tm0, 1));
        tm0 = fmaxf(tm0, __shfl_xor_sync(0xffffffffu, tm0, 2));
        tm1 = fmaxf(tm1, __shfl_xor_sync(0xffffffffu, tm1, 1));
        tm1 = fmaxf(tm1, __shfl_xor_sync(0xffffffffu, tm1, 2));
        float nm0 = fmaxf(m0, tm0), nm1 = fmaxf(m1, tm1);
        float a0 = exp2f(m0 - nm0), a1 = exp2f(m1 - nm1);
        m0 = nm0; m1 = nm1;

        float rs0 = 0.f, rs1 = 0.f;
#pragma unroll
        for (int nt = 0; nt < 8; ++nt) {
            float p0 = exp2f(sc[nt][0] - nm0);
            float p1 = exp2f(sc[nt][1] - nm0);
            float p2 = exp2f(sc[nt][2] - nm1);
            float p3 = exp2f(sc[nt][3] - nm1);
            rs0 += p0 + p1;
            rs1 += p2 + p3;
            *(float2*)(Pw + lr * PS_ + nt * 8 + lk * 2) =
                make_float2(to_tf32(p0), to_tf32(p1));
            *(float2*)(Pw + (lr + 8) * PS_ + nt * 8 + lk * 2) =
                make_float2(to_tf32(p2), to_tf32(p3));
        }
        rs0 += __shfl_xor_sync(0xffffffffu, rs0, 1);
        rs0 += __shfl_xor_sync(0xffffffffu, rs0, 2);
        rs1 += __shfl_xor_sync(0xffffffffu, rs1, 1);
        rs1 += __shfl_xor_sync(0xffffffffu, rs1, 2);
        l0 = l0 * a0 + rs0;
        l1 = l1 * a1 + rs1;
#pragma unroll
        for (int nt = 0; nt < 8; ++nt) {
            o[nt][0] *= a0; o[nt][1] *= a0;
            o[nt][2] *= a1; o[nt][3] *= a1;
        }
        __syncthreads();   // VT transposed + visible

        // ---- O += P @ V  (P A-frags + VT B-frags via LDSM) ----
#pragma unroll
        for (int ks = 0; ks < 8; ++ks) {
            uint32_t pa[4];
            ldsm4(pa, Pwb + p_loff + (uint32_t)(ks * 8) * 4);
#pragma unroll
            for (int ntp = 0; ntp < 4; ++ntp) {
                uint32_t vb[4];
                ldsm4(vb, VTb + vt_loff + (uint32_t)(ntp * 16 * VT_S + ks * 8) * 4);
                mma1688(o[2 * ntp],     pa, vb[0], vb[1]);
                mma1688(o[2 * ntp + 1], pa, vb[2], vb[3]);
            }
        }
    }

    float inv0 = 1.f / l0, inv1 = 1.f / l1;
    int r = b * S_ + q0 + wid * 16 + lr;
    float* ob = g_o + (size_t)r * H_ + head * HD_;
#pragma unroll
    for (int nt = 0; nt < 8; ++nt) {
        *(float2*)(ob + nt * 8 + lk * 2) =
            make_float2(to_tf32(o[nt][0] * inv0), to_tf32(o[nt][1] * inv0));
        *(float2*)(ob + (size_t)8 * H_ + nt * 8 + lk * 2) =
            make_float2(to_tf32(o[nt][2] * inv1), to_tf32(o[nt][3] * inv1));
    }
}

// ============================================================
extern "C" void kernel_launch(void* const* d_in, const int* in_sizes, int n_in,
                              void* d_out, int out_size) {
    (void)in_sizes; (void)n_in; (void)out_size;
    const float* x     = (const float*)d_in[0];
    const float* ada   = (const float*)d_in[1];
    const float* freqs = (const float*)d_in[2];
    const float* w_qkv = (const float*)d_in[3];
    const float* w_o   = (const float*)d_in[4];
    const float* ln_w  = (const float*)d_in[5];
    const float* mod_w = (const float*)d_in[6];
    const float* mod_b = (const float*)d_in[7];
    const float* qn_w  = (const float*)d_in[8];
    const float* kn_w  = (const float*)d_in[9];
    float* out = (float*)d_out;

    const int SMEM_DYN = 4 * STG_BYTES;   // 81920 bytes
    cudaFuncSetAttribute(tc_gemm, cudaFuncAttributeMaxDynamicSharedMemorySize, SMEM_DYN);
    cudaFuncSetAttribute(attn_mma_kernel, cudaFuncAttributeMaxDynamicSharedMemorySize, ATT_SMEM);

    mod_kernel<<<768, 256>>>(ada, mod_w, mod_b);
    round_w_kernel<<<4096, 256>>>(w_qkv, w_o);
    ln_mod_kernel<<<R_, 256>>>(x, ln_w);
    tc_gemm<<<dim3(H3_ / 128, R_ / 128), 256, SMEM_DYN>>>(nullptr, H3_, 0);
    qknorm_rope_kernel<<<R_, 256>>>(freqs, qn_w, kn_w);
    attn_mma_kernel<<<dim3(S_ / 128, B_ * NH_), 256, ATT_SMEM>>>();
    tc_gemm<<<dim3(H_ / 128, R_ / 128), 256, SMEM_DYN>>>(out, H_, 1);
}

// round 14
// speedup vs baseline: 3.0611x; 1.0011x over previous
#include <cuda_runtime.h>
#include <cstdint>
#include <math.h>

#define B_ 2
#define S_ 2048
#define H_ 1024
#define NH_ 16
#define HD_ 64
#define H3_ 3072
#define R_ 4096   // B*S

// ---- scratch (static device globals; no runtime allocation) ----
__device__ __align__(256) float g_mod[B_ * H3_];           // [B, 3H] (scale|shift|gate)
__device__ __align__(256) float g_h[(size_t)R_ * H_];      // modulated LN output (tf32-rounded)
__device__ __align__(256) float g_qkv[(size_t)R_ * H3_];   // qkv projections (tf32-rounded)
__device__ __align__(256) float g_o[(size_t)R_ * H_];      // attention output (tf32-rounded)
__device__ __align__(256) float g_w1[(size_t)H3_ * H_];    // tf32-rounded w_qkv
__device__ __align__(256) float g_w2[(size_t)H_ * H_];     // tf32-rounded w_o

// ============================================================
// helpers
// ============================================================
__device__ __forceinline__ float warp_sum(float v) {
#pragma unroll
    for (int o = 16; o; o >>= 1) v += __shfl_xor_sync(0xffffffffu, v, o);
    return v;
}

__device__ __forceinline__ float to_tf32(float x) {
    float r;
    asm("cvt.rna.tf32.f32 %0, %1;" : "=f"(r) : "f"(x));
    return r;
}

__device__ __forceinline__ uint32_t cvta_smem(const void* p) {
    uint32_t a;
    asm("{ .reg .u64 t; cvta.to.shared.u64 t, %1; cvt.u32.u64 %0, t; }" : "=r"(a) : "l"(p));
    return a;
}

__device__ __forceinline__ void cp_async16(uint32_t dst, const void* src) {
    asm volatile("cp.async.cg.shared.global [%0], [%1], 16;" :: "r"(dst), "l"(src));
}

// mma.sync tf32: D[16x8] += A[16x8] * B[8x8]   (portable, sm_80+)
__device__ __forceinline__ void mma1688(float* d, const uint32_t* a, uint32_t b0, uint32_t b1) {
    asm volatile(
        "mma.sync.aligned.m16n8k8.row.col.f32.tf32.tf32.f32 "
        "{%0,%1,%2,%3}, {%4,%5,%6,%7}, {%8,%9}, {%0,%1,%2,%3};"
        : "+f"(d[0]), "+f"(d[1]), "+f"(d[2]), "+f"(d[3])
        : "r"(a[0]), "r"(a[1]), "r"(a[2]), "r"(a[3]), "r"(b0), "r"(b1));
}

// ldmatrix x4: four m8n8 b16 matrices (lane i supplies row addr for matrix i/8)
__device__ __forceinline__ void ldsm4(uint32_t* r, uint32_t addr) {
    asm volatile("ldmatrix.sync.aligned.m8n8.x4.shared.b16 {%0,%1,%2,%3}, [%4];"
                 : "=r"(r[0]), "=r"(r[1]), "=r"(r[2]), "=r"(r[3]) : "r"(addr));
}

// ============================================================
// 0) round weights fp32 -> tf32 (RNA)
// ============================================================
__global__ void __launch_bounds__(256) round_w_kernel(const float* __restrict__ wq,
                                                      const float* __restrict__ wo) {
    const size_t n1 = (size_t)H3_ * H_ / 4;
    const size_t n2 = (size_t)H_ * H_ / 4;
    size_t i = (size_t)blockIdx.x * 256 + threadIdx.x;
    if (i < n1) {
        float4 v = ((const float4*)wq)[i];
        v.x = to_tf32(v.x); v.y = to_tf32(v.y); v.z = to_tf32(v.z); v.w = to_tf32(v.w);
        ((float4*)g_w1)[i] = v;
    } else if (i < n1 + n2) {
        size_t j = i - n1;
        float4 v = ((const float4*)wo)[j];
        v.x = to_tf32(v.x); v.y = to_tf32(v.y); v.z = to_tf32(v.z); v.w = to_tf32(v.w);
        ((float4*)g_w2)[j] = v;
    }
}

// ============================================================
// 1) mod = silu(ada) @ mod_w^T + mod_b       (one warp per output)
// ============================================================
__global__ void __launch_bounds__(256) mod_kernel(const float* __restrict__ ada,
                                                  const float* __restrict__ mw,
                                                  const float* __restrict__ mb) {
    int gw = (blockIdx.x * 256 + threadIdx.x) >> 5;
    int lane = threadIdx.x & 31;
    int b = gw / H3_, j = gw % H3_;
    const float* ar = ada + b * 1024;
    const float* wr = mw + (size_t)j * 1024;
    float acc = 0.f;
#pragma unroll 4
    for (int a = lane; a < 1024; a += 32) {
        float v = ar[a];
        float s = v / (1.f + __expf(-v));
        acc = fmaf(s, wr[a], acc);
    }
    acc = warp_sum(acc);
    if (lane == 0) g_mod[gw] = acc + mb[j];
}

// ============================================================
// 2) h = LN(x)*ln_w*(scale+1) + shift   (tf32-rounded for GEMM A)
// ============================================================
__global__ void __launch_bounds__(256) ln_mod_kernel(const float* __restrict__ x,
                                                     const float* __restrict__ ln_w) {
    int row = blockIdx.x;
    int tid = threadIdx.x;
    int b = row >> 11;

    float4 xv = ((const float4*)x)[(size_t)row * 256 + tid];
    float sum = xv.x + xv.y + xv.z + xv.w;
    float sq  = xv.x * xv.x + xv.y * xv.y + xv.z * xv.z + xv.w * xv.w;
    sum = warp_sum(sum);
    sq  = warp_sum(sq);

    __shared__ float rs[8], rq[8], mv[2];
    int warp = tid >> 5, lane = tid & 31;
    if (lane == 0) { rs[warp] = sum; rq[warp] = sq; }
    __syncthreads();
    if (tid == 0) {
        float s = 0.f, q = 0.f;
#pragma unroll
        for (int w = 0; w < 8; ++w) { s += rs[w]; q += rq[w]; }
        float mean = s * (1.f / 1024.f);
        float var  = q * (1.f / 1024.f) - mean * mean;
        mv[0] = mean;
        mv[1] = rsqrtf(var + 1e-5f);
    }
    __syncthreads();
    float mean = mv[0], rstd = mv[1];

    float4 lw = ((const float4*)ln_w)[tid];
    const float* mp = g_mod + b * H3_;
    float4 sc = ((const float4*)mp)[tid];
    float4 sh = ((const float4*)(mp + H_))[tid];

    float4 h;
    h.x = to_tf32((xv.x - mean) * rstd * lw.x * (sc.x + 1.f) + sh.x);
    h.y = to_tf32((xv.y - mean) * rstd * lw.y * (sc.y + 1.f) + sh.y);
    h.z = to_tf32((xv.z - mean) * rstd * lw.z * (sc.z + 1.f) + sh.z);
    h.w = to_tf32((xv.w - mean) * rstd * lw.w * (sc.w + 1.f) + sh.w);
    ((float4*)g_h)[(size_t)row * 256 + tid] = h;
}

// ============================================================
// 3/6) tf32 mma.sync GEMM NT: C[M,N] = A[M,1024] * B[N,1024]^T
//      128x128 CTA tile, BK=16, 4-stage cp.async, 8 warps (32x64 each).
//      Single barrier per k-iter: wait -> sync -> issue load(it+3) -> MMAs.
// ============================================================
#define GK_ 1024
#define GNIT 64                 // GK_/16
#define STG_FLOATS 5120         // per stage: A(2560) + B(2560)
#define STG_BYTES  20480

__device__ __forceinline__ void gemm_load_stage(uint32_t sb, const float* A, const float* Bm,
                                                int row0, int col0, int it, int tid) {
    int s = it & 3;
    int krow = it * 16;
    int r = tid >> 1;                 // 0..127
    int off = (tid & 1) * 8;          // 0 or 8 floats
    uint32_t base = sb + s * STG_BYTES;
    const float* ga = A + (size_t)(row0 + r) * GK_ + krow + off;
    uint32_t da = base + (r * 20 + off) * 4;
    cp_async16(da, ga);
    cp_async16(da + 16, ga + 4);
    const float* gb = Bm + (size_t)(col0 + r) * GK_ + krow + off;
    uint32_t db = base + 10240 + (r * 20 + off) * 4;   // B tile: +10240 bytes
    cp_async16(db, gb);
    cp_async16(db + 16, gb + 4);
    asm volatile("cp.async.commit_group;" ::: "memory");
}

__global__ void __launch_bounds__(256, 2) tc_gemm(float* __restrict__ Cext, int N, int mode) {
    extern __shared__ float sm[];
    const float* A  = mode ? g_o : g_h;
    const float* Bm = mode ? g_w2 : g_w1;
    float* C = mode ? Cext : g_qkv;

    uint32_t sb = cvta_smem(sm);
    int tid = threadIdx.x;
    int wid = tid >> 5, lane = tid & 31;
    int warp_m = wid & 3, warp_n = wid >> 2;
    int row0 = blockIdx.y << 7, col0 = blockIdx.x << 7;

    int sub = lane & 7, mi = lane >> 3;
    // A-frag: m0..m3 = (rows+0,k+0),(rows+8,k+0),(rows+0,k+4),(rows+8,k+4)
    uint32_t a_off = ((uint32_t)(((mi & 1) * 8 + sub) * 20 + (mi >> 1) * 4)) * 4;
    // B-frag pair (nt, nt+1): m0..m3 = (nt,k0),(nt,k4),(nt+1,k0),(nt+1,k4)
    uint32_t b_off = 10240u + ((uint32_t)(((mi >> 1) * 8 + sub) * 20 + (mi & 1) * 4)) * 4;

    float acc[2][8][4];
#pragma unroll
    for (int i = 0; i < 2; ++i)
#pragma unroll
        for (int j = 0; j < 8; ++j)
#pragma unroll
            for (int q = 0; q < 4; ++q) acc[i][j][q] = 0.f;

    gemm_load_stage(sb, A, Bm, row0, col0, 0, tid);
    gemm_load_stage(sb, A, Bm, row0, col0, 1, tid);
    gemm_load_stage(sb, A, Bm, row0, col0, 2, tid);

    for (int it = 0; it < GNIT; ++it) {
        asm volatile("cp.async.wait_group 2;" ::: "memory");   // stage it resident
        __syncthreads();   // all warps see stage it; all done reading stage (it+3)&3
        if (it + 3 < GNIT) gemm_load_stage(sb, A, Bm, row0, col0, it + 3, tid);

        uint32_t st = sb + (it & 3) * STG_BYTES;
#pragma unroll
        for (int k8 = 0; k8 < 16; k8 += 8) {
            uint32_t a0[4], a1[4];
            ldsm4(a0, st + a_off + (uint32_t)((warp_m * 32) * 20 + k8) * 4);
            ldsm4(a1, st + a_off + (uint32_t)((warp_m * 32 + 16) * 20 + k8) * 4);
#pragma unroll
            for (int ntp = 0; ntp < 4; ++ntp) {
                uint32_t bb[4];
                ldsm4(bb, st + b_off + (uint32_t)((warp_n * 64 + ntp * 16) * 20 + k8) * 4);
                mma1688(acc[0][2 * ntp],     a0, bb[0], bb[1]);
                mma1688(acc[1][2 * ntp],     a1, bb[0], bb[1]);
                mma1688(acc[0][2 * ntp + 1], a0, bb[2], bb[3]);
                mma1688(acc[1][2 * ntp + 1], a1, bb[2], bb[3]);
            }
        }
    }

    int lr = lane >> 2, lk = lane & 3;
    // epilogue (mode 0: round to tf32 for attention consumers; mode 1: gate)
#pragma unroll
    for (int mt = 0; mt < 2; ++mt) {
        int r = row0 + warp_m * 32 + mt * 16 + lr;
        int gb = (r >> 11) * H3_ + 2 * H_;
#pragma unroll
        for (int nt = 0; nt < 8; ++nt) {
            int c = col0 + warp_n * 64 + nt * 8 + lk * 2;
            float2 v0 = make_float2(acc[mt][nt][0], acc[mt][nt][1]);
            float2 v1 = make_float2(acc[mt][nt][2], acc[mt][nt][3]);
            if (mode) {
                float gx = g_mod[gb + c], gy = g_mod[gb + c + 1];
                v0.x *= gx; v0.y *= gy;
                v1.x *= gx; v1.y *= gy;
            } else {
                v0.x = to_tf32(v0.x); v0.y = to_tf32(v0.y);
                v1.x = to_tf32(v1.x); v1.y = to_tf32(v1.y);
            }
            *(float2*)(C + (size_t)r * N + c) = v0;
            *(float2*)(C + (size_t)(r + 8) * N + c) = v1;
        }
    }
}

// ============================================================
// 4) per-head QK layernorm + RoPE, in place on g_qkv
//    q gets 0.125*log2(e) folded in (softmax uses exp2); outputs tf32-rounded
// ============================================================
__global__ void __launch_bounds__(256) qknorm_rope_kernel(const float* __restrict__ freqs,
                                                          const float* __restrict__ qn_w,
                                                          const float* __restrict__ kn_w) {
    int row = blockIdx.x;
    int s = row & (S_ - 1);
    int warp = threadIdx.x >> 5;
    int lane = threadIdx.x & 31;

    float f0 = freqs[(s * 32 + lane) * 2 + 0];
    float f1 = freqs[(s * 32 + lane) * 2 + 1];

    for (int task = warp; task < 32; task += 8) {
        int type = task >> 4;
        int head = task & 15;
        size_t base = (size_t)row * H3_ + type * H_ + head * HD_;
        float v0 = g_qkv[base + lane * 2];
        float v1 = g_qkv[base + lane * 2 + 1];
        float sum = warp_sum(v0 + v1);
        float sq  = warp_sum(v0 * v0 + v1 * v1);
        float mean = sum * (1.f / 64.f);
        float var  = sq * (1.f / 64.f) - mean * mean;
        float rstd = rsqrtf(var + 1e-5f);
        const float* w = type ? kn_w : qn_w;
        float n0 = (v0 - mean) * rstd * w[lane * 2];
        float n1 = (v1 - mean) * rstd * w[lane * 2 + 1];
        float r0 = n0 * f0 - n1 * f1;
        float r1 = n1 * f0 + n0 * f1;
        float qs = type ? 1.f : (0.125f * 1.44269504088896340736f);
        g_qkv[base + lane * 2]     = to_tf32(r0 * qs);
        g_qkv[base + lane * 2 + 1] = to_tf32(r1 * qs);
    }
}

// ============================================================
// 5) flash attention (non-causal), tf32 mma.sync + ldmatrix, base-2 softmax
//    grid = (S/128, B*NH), 256 threads (8 warps x m16 q-rows)
// ============================================================
#define KS_ 68
#define VS_ 72
#define VT_S 68
#define PS_ 68
#define OFF_VB (2 * 64 * KS_)            // 8704
#define OFF_VT (OFF_VB + 2 * 64 * VS_)   // 17920
#define OFF_P  (OFF_VT + 64 * VT_S)      // 22272
#define ATT_SMEM ((OFF_P + 8 * 16 * PS_) * 4)   // 123904 bytes

__device__ __forceinline__ void attn_load_kv(uint32_t sb, const float* gkv, int t, int tid) {
    int s = t & 1;
    int r = tid >> 2;                 // 0..63 (key within tile)
    int cc = (tid & 3) * 16;          // dim chunk
    const float* kg = gkv + (size_t)(t * 64 + r) * H3_ + cc;
    const float* vg = kg + H_;
    uint32_t kd = sb + (uint32_t)(s * 64 * KS_ + r * KS_ + cc) * 4;
    uint32_t vd = sb + (uint32_t)(OFF_VB + s * 64 * VS_ + r * VS_ + cc) * 4;
#pragma unroll
    for (int i = 0; i < 4; ++i) {
        cp_async16(kd + i * 16, kg + i * 4);
        cp_async16(vd + i * 16, vg + i * 4);
    }
    asm volatile("cp.async.commit_group;" ::: "memory");
}

__global__ void __launch_bounds__(256, 1) attn_mma_kernel() {
    extern __shared__ float sm[];
    uint32_t sb = cvta_smem(sm);

    int tid = threadIdx.x, wid = tid >> 5, lane = tid & 31;
    int lr = lane >> 2, lk = lane & 3;
    int sub = lane & 7, mi = lane >> 3;
    int q0 = blockIdx.x << 7;
    int b = blockIdx.y >> 4, head = blockIdx.y & 15;

    const float* gkv = g_qkv + (size_t)b * S_ * H3_ + H_ + head * HD_;  // K base (V = +H_)

    // per-lane LDSM offsets (bytes)
    uint32_t k_loff = (uint32_t)(sub * KS_ + (mi >> 1) * 8 + (mi & 1) * 4) * 4;
    uint32_t vt_loff = (uint32_t)(((mi >> 1) * 8 + sub) * VT_S + (mi & 1) * 4) * 4;
    uint32_t p_loff = (uint32_t)(((mi & 1) * 8 + sub) * PS_ + (mi >> 1) * 4) * 4;

    // Q fragments (registers for the whole kernel; pre-scaled & tf32)
    uint32_t qa[8][4];
    {
        const float* Qb = g_qkv + (size_t)(b * S_ + q0 + wid * 16) * H3_ + head * HD_;
#pragma unroll
        for (int ks = 0; ks < 8; ++ks) {
            qa[ks][0] = __float_as_uint(Qb[(size_t)lr * H3_ + ks * 8 + lk]);
            qa[ks][1] = __float_as_uint(Qb[(size_t)(lr + 8) * H3_ + ks * 8 + lk]);
            qa[ks][2] = __float_as_uint(Qb[(size_t)lr * H3_ + ks * 8 + lk + 4]);
            qa[ks][3] = __float_as_uint(Qb[(size_t)(lr + 8) * H3_ + ks * 8 + lk + 4]);
        }
    }

    float m0 = -1e30f, m1 = -1e30f, l0 = 0.f, l1 = 0.f;
    float o[8][4];
#pragma unroll
    for (int nt = 0; nt < 8; ++nt)
#pragma unroll
        for (int q = 0; q < 4; ++q) o[nt][q] = 0.f;

    float* Pw = sm + OFF_P + wid * 16 * PS_;
    uint32_t Pwb = sb + (uint32_t)(OFF_P + wid * 16 * PS_) * 4;
    uint32_t VTb = sb + (uint32_t)OFF_VT * 4;

    attn_load_kv(sb, gkv, 0, tid);

    for (int t = 0; t < 32; ++t) {
        asm volatile("cp.async.wait_group 0;" ::: "memory");   // tile t resident
        __syncthreads();   // visible to all; prev iter's reads of buffer (t+1)&1 done
        if (t < 31) attn_load_kv(sb, gkv, t + 1, tid);

        // ---- transpose V tile: Vbuf[key][dim] -> VT[dim][key] ----
        {
            int key = tid & 63, dbase = (tid >> 6) * 16;
            const float* src = sm + OFF_VB + (t & 1) * 64 * VS_ + key * VS_ + dbase;
            float4 va = ((const float4*)src)[0];
            float4 vb4 = ((const float4*)src)[1];
            float4 vc = ((const float4*)src)[2];
            float4 vd = ((const float4*)src)[3];
            float vv[16] = {va.x, va.y, va.z, va.w, vb4.x, vb4.y, vb4.z, vb4.w,
                            vc.x, vc.y, vc.z, vc.w, vd.x, vd.y, vd.z, vd.w};
            float* vt = sm + OFF_VT;
#pragma unroll
            for (int d = 0; d < 16; ++d) vt[(dbase + d) * VT_S + key] = vv[d];
        }

        uint32_t Kst = sb + (uint32_t)((t & 1) * 64 * KS_) * 4;

        // ---- scores = Q @ K^T (pre-scaled, base-2 domain) ----
        float sc[8][4];
#pragma unroll
        for (int nt = 0; nt < 8; ++nt) {
            uint32_t kb[16];
#pragma unroll
            for (int p = 0; p < 4; ++p)
                ldsm4(kb + 4 * p, Kst + k_loff + (uint32_t)(nt * 8 * KS_ + p * 16) * 4);
#pragma unroll
            for (int q = 0; q < 4; ++q) sc[nt][q] = 0.f;
#pragma unroll
            for (int ks = 0; ks < 8; ++ks)
                mma1688(sc[nt], qa[ks], kb[2 * ks], kb[2 * ks + 1]);
        }

        // ---- online softmax, base 2 (rows lr, lr+8; quad lanes share a row) ----
        float tm0 = -1e30f, tm1 = -1e30f;
#pragma unroll
        for (int nt = 0; nt < 8; ++nt) {
            tm0 = fmaxf(tm0, fmaxf(sc[nt][0], sc[nt][1]));
            tm1 = fmaxf(tm1, fmaxf(sc[nt][2], sc[nt][3]));
        }
        tm0 = fmaxf(tm0, __shfl_xor_sync(0xffffffffu, tm0, 1));
        tm0 = fmaxf(tm0, __shfl_xor_sync(0xffffffffu, tm0, 2));
        tm1 = fmaxf(tm1, __shfl_xor_sync(0xffffffffu, tm1, 1));
        tm1 = fmaxf(tm1, __shfl_xor_sync(0xffffffffu, tm1, 2));
        float nm0 = fmaxf(m0, tm0), nm1 = fmaxf(m1, tm1);
        float a0 = exp2f(m0 - nm0), a1 = exp2f(m1 - nm1);
        m0 = nm0; m1 = nm1;

        float rs0 = 0.f, rs1 = 0.f;
#pragma unroll
        for (int nt = 0; nt < 8; ++nt) {
            float p0 = exp2f(sc[nt][0] - nm0);
            float p1 = exp2f(sc[nt][1] - nm0);
            float p2 = exp2f(sc[nt][2] - nm1);
            float p3 = exp2f(sc[nt][3] - nm1);
            rs0 += p0 + p1;
            rs1 += p2 + p3;
            *(float2*)(Pw + lr * PS_ + nt * 8 + lk * 2) =
                make_float2(to_tf32(p0), to_tf32(p1));
            *(float2*)(Pw + (lr + 8) * PS_ + nt * 8 + lk * 2) =
                make_float2(to_tf32(p2), to_tf32(p3));
        }
        rs0 += __shfl_xor_sync(0xffffffffu, rs0, 1);
        rs0 += __shfl_xor_sync(0xffffffffu, rs0, 2);
        rs1 += __shfl_xor_sync(0xffffffffu, rs1, 1);
        rs1 += __shfl_xor_sync(0xffffffffu, rs1, 2);
        l0 = l0 * a0 + rs0;
        l1 = l1 * a1 + rs1;
#pragma unroll
        for (int nt = 0; nt < 8; ++nt) {
            o[nt][0] *= a0; o[nt][1] *= a0;
            o[nt][2] *= a1; o[nt][3] *= a1;
        }
        __syncthreads();   // VT transposed + visible

        // ---- O += P @ V  (P A-frags + VT B-frags via LDSM) ----
#pragma unroll
        for (int ks = 0; ks < 8; ++ks) {
            uint32_t pa[4];
            ldsm4(pa, Pwb + p_loff + (uint32_t)(ks * 8) * 4);
#pragma unroll
            for (int ntp = 0; ntp < 4; ++ntp) {
                uint32_t vb[4];
                ldsm4(vb, VTb + vt_loff + (uint32_t)(ntp * 16 * VT_S + ks * 8) * 4);
                mma1688(o[2 * ntp],     pa, vb[0], vb[1]);
                mma1688(o[2 * ntp + 1], pa, vb[2], vb[3]);
            }
        }
    }

    float inv0 = 1.f / l0, inv1 = 1.f / l1;
    int r = b * S_ + q0 + wid * 16 + lr;
    float* ob = g_o + (size_t)r * H_ + head * HD_;
#pragma unroll
    for (int nt = 0; nt < 8; ++nt) {
        *(float2*)(ob + nt * 8 + lk * 2) =
            make_float2(to_tf32(o[nt][0] * inv0), to_tf32(o[nt][1] * inv0));
        *(float2*)(ob + (size_t)8 * H_ + nt * 8 + lk * 2) =
            make_float2(to_tf32(o[nt][2] * inv1), to_tf32(o[nt][3] * inv1));
    }
}

// ============================================================
extern "C" void kernel_launch(void* const* d_in, const int* in_sizes, int n_in,
                              void* d_out, int out_size) {
    (void)in_sizes; (void)n_in; (void)out_size;
    const float* x     = (const float*)d_in[0];
    const float* ada   = (const float*)d_in[1];
    const float* freqs = (const float*)d_in[2];
    const float* w_qkv = (const float*)d_in[3];
    const float* w_o   = (const float*)d_in[4];
    const float* ln_w  = (const float*)d_in[5];
    const float* mod_w = (const float*)d_in[6];
    const float* mod_b = (const float*)d_in[7];
    const float* qn_w  = (const float*)d_in[8];
    const float* kn_w  = (const float*)d_in[9];
    float* out = (float*)d_out;

    const int SMEM_DYN = 4 * STG_BYTES;   // 81920 bytes
    cudaFuncSetAttribute(tc_gemm, cudaFuncAttributeMaxDynamicSharedMemorySize, SMEM_DYN);
    cudaFuncSetAttribute(attn_mma_kernel, cudaFuncAttributeMaxDynamicSharedMemorySize, ATT_SMEM);

    mod_kernel<<<768, 256>>>(ada, mod_w, mod_b);
    round_w_kernel<<<4096, 256>>>(w_qkv, w_o);
    ln_mod_kernel<<<R_, 256>>>(x, ln_w);
    tc_gemm<<<dim3(H3_ / 128, R_ / 128), 256, SMEM_DYN>>>(nullptr, H3_, 0);
    qknorm_rope_kernel<<<R_, 256>>>(freqs, qn_w, kn_w);
    attn_mma_kernel<<<dim3(S_ / 128, B_ * NH_), 256, ATT_SMEM>>>();
    tc_gemm<<<dim3(H_ / 128, R_ / 128), 256, SMEM_DYN>>>(out, H_, 1);
}